// round 1
// baseline (speedup 1.0000x reference)
#include <cuda_runtime.h>

// Problem constants (fixed for this problem instance)
#define GDIM 620
#define HH   150
#define HP   160      // H padded to 160 for clean tiling (pad cols are exact zeros)
#define TP   128      // pairs per block in main kernel
#define KC   8        // k-chunk
#define NT   256      // threads per block

#define MMAX 1024
#define PMAX 50176

// Scratch (no allocation allowed -> __device__ globals)
__device__ float d_Apad[MMAX * HP];     // g_i @ W1[0:620]     , padded h
__device__ float d_Bpad[MMAX * HP];     // g_i @ W1[620:1240]  , padded h
__device__ float d_distT[9 * HP];       // dist_emb @ W1[1860:1880] + b1
__device__ float d_genT[8 * HP];        // genre_emb @ W1[1880:1900]
__device__ float d_spkT[3 * HP];        // speaker_emb @ W1[1900:1920]
__device__ float d_scores[PMAX];        // per-pair coref logits
__device__ int   d_starts[MMAX + 2];    // segment starts (mention_ids sorted)

// ---------------------------------------------------------------------------
// Fill output with pad value 1000.0, out[0][0] = 1.0 (leading epsilon row)
// ---------------------------------------------------------------------------
__global__ void fill_out_k(float* __restrict__ out, int n) {
    int i = blockIdx.x * blockDim.x + threadIdx.x;
    if (i < n) out[i] = (i == 0) ? 1.0f : 1000.0f;
}

// ---------------------------------------------------------------------------
// Tiny phi tables: rows 0..8 dist (+b1), 9..16 genre, 17..19 speaker
// ---------------------------------------------------------------------------
__global__ void tables_k(const float* __restrict__ de, const float* __restrict__ ge,
                         const float* __restrict__ se, const float* __restrict__ W1,
                         const float* __restrict__ b1) {
    for (int e = threadIdx.x; e < 20 * HP; e += blockDim.x) {
        int row = e / HP, h = e % HP;
        const float* emb; int dbase; float* dst; float acc;
        if (row < 9)       { emb = de + row * 20;        dbase = 3 * GDIM;      dst = d_distT + row * HP + h;        acc = (h < HH) ? b1[h] : 0.0f; }
        else if (row < 17) { emb = ge + (row - 9) * 20;  dbase = 3 * GDIM + 20; dst = d_genT  + (row - 9) * HP + h;  acc = 0.0f; }
        else               { emb = se + (row - 17) * 20; dbase = 3 * GDIM + 40; dst = d_spkT  + (row - 17) * HP + h; acc = 0.0f; }
        if (h < HH) {
            #pragma unroll
            for (int k = 0; k < 20; k++) acc += emb[k] * W1[(dbase + k) * HH + h];
        }
        *dst = acc;
    }
}

// ---------------------------------------------------------------------------
// Precompute A = g @ W1a, B = g @ W1b  (8 mentions per block)
// ---------------------------------------------------------------------------
__global__ __launch_bounds__(NT) void ab_k(const float* __restrict__ g,
                                           const float* __restrict__ W1, int M) {
    __shared__ float gs[8][GDIM];
    int m0 = blockIdx.x * 8;
    for (int e = threadIdx.x; e < 8 * GDIM; e += NT) {
        int mm = e / GDIM, d = e % GDIM;
        int m = m0 + mm;
        gs[mm][d] = (m < M) ? g[m * GDIM + d] : 0.0f;
    }
    __syncthreads();
    for (int c = threadIdx.x; c < 2 * HP; c += NT) {
        int h = c % HP;
        int which = c / HP;  // 0 -> A (rows 0..619), 1 -> B (rows 620..1239)
        float acc[8] = {0.f, 0.f, 0.f, 0.f, 0.f, 0.f, 0.f, 0.f};
        if (h < HH) {
            const float* w = W1 + (which ? GDIM * HH : 0) + h;
            for (int d = 0; d < GDIM; d++) {
                float wv = __ldg(&w[d * HH]);
                #pragma unroll
                for (int mm = 0; mm < 8; mm++) acc[mm] += gs[mm][d] * wv;
            }
        }
        float* dst = which ? d_Bpad : d_Apad;
        #pragma unroll
        for (int mm = 0; mm < 8; mm++) {
            int m = m0 + mm;
            if (m < M) dst[m * HP + h] = acc[mm];
        }
    }
}

// ---------------------------------------------------------------------------
// Segment starts: lower_bound(mention_ids, m), mention_ids sorted
// ---------------------------------------------------------------------------
__global__ void starts_k(const int* __restrict__ mids, int P, int M) {
    int m = blockIdx.x * blockDim.x + threadIdx.x;
    if (m > M) return;
    int lo = 0, hi = P;
    while (lo < hi) {
        int mid = (lo + hi) >> 1;
        if (mids[mid] < m) lo = mid + 1; else hi = mid;
    }
    d_starts[m] = lo;
}

// ---------------------------------------------------------------------------
// Main: per-pair  relu( A[i]+B[j]+phiT + (g[i]*g[j]) @ W1c ) @ W2  + scores
// Block: 128 pairs x 160 h, 256 threads (16 pair-groups x 16 h-lanes),
// 8x10 register tile per thread.
// ---------------------------------------------------------------------------
__global__ __launch_bounds__(NT) void pair_k(
    const float* __restrict__ g,   const float* __restrict__ W1,
    const float* __restrict__ W2,  const float* __restrict__ b2,
    const float* __restrict__ ms,
    const int* __restrict__ mids,  const int* __restrict__ aids,
    const int* __restrict__ dists, const int* __restrict__ gens,
    const int* __restrict__ spks,  int P)
{
    __shared__ int   si[TP], sj[TP], sd[TP], sg[TP], ss[TP];
    __shared__ float Xs[KC][TP + 4];   // stride 132: conflict-free, float4-aligned
    __shared__ float Ws[KC][HP];
    __shared__ float w2s[HP];

    const int tid = threadIdx.x;
    const int pb  = blockIdx.x * TP;

    if (tid < TP) {
        int p  = pb + tid;
        int ok = (p < P);
        si[tid] = ok ? mids[p] : 0;
        sj[tid] = ok ? aids[p] : 0;
        int dd  = ok ? dists[p] : 0;
        sd[tid] = (dd >= 1) + (dd >= 2) + (dd >= 3) + (dd >= 4) +
                  (dd >= 8) + (dd >= 16) + (dd >= 32) + (dd >= 64);
        sg[tid] = ok ? gens[p] : 0;
        ss[tid] = ok ? spks[p] : 0;
    }
    if (tid < HP) w2s[tid] = (tid < HH) ? W2[tid] : 0.0f;
    __syncthreads();

    const int px = tid >> 4;     // 0..15 : pair group (8 pairs each)
    const int hx = tid & 15;     // 0..15 : h lane (h = hx + 16q)
    const int p0 = px * 8;

    float acc[8][10];
    #pragma unroll
    for (int r = 0; r < 8; r++) {
        int pp  = p0 + r;
        int ib  = si[pp] * HP, jb = sj[pp] * HP;
        int dbb = sd[pp] * HP, gb = sg[pp] * HP, sb = ss[pp] * HP;
        #pragma unroll
        for (int q = 0; q < 10; q++) {
            int h = hx + 16 * q;
            acc[r][q] = d_Apad[ib + h] + d_Bpad[jb + h] +
                        d_distT[dbb + h] + d_genT[gb + h] + d_spkT[sb + h];
        }
    }

    const float* W1c = W1 + (2 * GDIM) * HH;   // Hadamard-term weights

    #pragma unroll 1
    for (int ko = 0; ko < GDIM; ko += KC) {
        __syncthreads();
        // Xs[k][p] = g[i_p][ko+k] * g[j_p][ko+k]   (1024 elems, 4/thread)
        #pragma unroll
        for (int it = 0; it < (KC * TP) / NT; it++) {
            int e  = tid + NT * it;
            int pp = e >> 3, k = e & 7;
            int kk = ko + k;
            float v = 0.0f;
            if (kk < GDIM)
                v = __ldg(&g[si[pp] * GDIM + kk]) * __ldg(&g[sj[pp] * GDIM + kk]);
            Xs[k][pp] = v;
        }
        // Ws[k][h] = W1c[(ko+k)*HH + h]   (1280 elems, 5/thread)
        #pragma unroll
        for (int it = 0; it < (KC * HP) / NT; it++) {
            int e = tid + NT * it;
            int k = e / HP, h = e % HP;
            int kk = ko + k;
            float v = 0.0f;
            if (kk < GDIM && h < HH) v = __ldg(&W1c[kk * HH + h]);
            Ws[k][h] = v;
        }
        __syncthreads();

        #pragma unroll
        for (int k = 0; k < KC; k++) {
            float4 xa = *(const float4*)&Xs[k][p0];
            float4 xb = *(const float4*)&Xs[k][p0 + 4];
            float xv[8] = {xa.x, xa.y, xa.z, xa.w, xb.x, xb.y, xb.z, xb.w};
            float w[10];
            #pragma unroll
            for (int q = 0; q < 10; q++) w[q] = Ws[k][hx + 16 * q];
            #pragma unroll
            for (int r = 0; r < 8; r++)
                #pragma unroll
                for (int q = 0; q < 10; q++)
                    acc[r][q] = fmaf(xv[r], w[q], acc[r][q]);
        }
    }

    // Epilogue: relu, dot with W2, reduce across 16 h-lanes, add mention scores
    float b2v = __ldg(b2);
    #pragma unroll
    for (int r = 0; r < 8; r++) {
        float s = 0.0f;
        #pragma unroll
        for (int q = 0; q < 10; q++) {
            float hv = acc[r][q];
            hv = hv > 0.0f ? hv : 0.0f;
            s = fmaf(hv, w2s[hx + 16 * q], s);
        }
        #pragma unroll
        for (int off = 8; off >= 1; off >>= 1)
            s += __shfl_xor_sync(0xffffffffu, s, off);
        if (hx == 0) {
            int p = pb + p0 + r;
            if (p < P)
                d_scores[p] = s + ms[si[p0 + r]] + ms[sj[p0 + r]] + b2v;
        }
    }
}

// ---------------------------------------------------------------------------
// Ragged softmax (+epsilon logit 0) and scatter into padded output.
// One warp per mention; out row = mention + 1.
// ---------------------------------------------------------------------------
__global__ void softmax_k(float* __restrict__ out, int M) {
    int warp = (blockIdx.x * blockDim.x + threadIdx.x) >> 5;
    int lane = threadIdx.x & 31;
    if (warp >= M) return;
    int s0 = d_starts[warp], s1 = d_starts[warp + 1];
    int n = s1 - s0;

    float mx = 0.0f;  // epsilon logit 0 always present
    for (int i = lane; i < n; i += 32) mx = fmaxf(mx, d_scores[s0 + i]);
    #pragma unroll
    for (int off = 16; off; off >>= 1) mx = fmaxf(mx, __shfl_xor_sync(0xffffffffu, mx, off));

    float sum = 0.0f;
    for (int i = lane; i < n; i += 32) sum += expf(d_scores[s0 + i] - mx);
    #pragma unroll
    for (int off = 16; off; off >>= 1) sum += __shfl_xor_sync(0xffffffffu, sum, off);

    float eps = expf(-mx);
    float inv = 1.0f / (sum + eps);
    float* row = out + (warp + 1) * 161;
    for (int i = lane; i < n; i += 32) row[i] = expf(d_scores[s0 + i] - mx) * inv;
    if (lane == 0) row[n] = eps * inv;
}

// ---------------------------------------------------------------------------
extern "C" void kernel_launch(void* const* d_in, const int* in_sizes, int n_in,
                              void* d_out, int out_size) {
    const float* g_i   = (const float*)d_in[0];
    const float* msc   = (const float*)d_in[1];
    const float* de    = (const float*)d_in[2];
    const float* ge    = (const float*)d_in[3];
    const float* se    = (const float*)d_in[4];
    const float* W1    = (const float*)d_in[5];
    const float* b1    = (const float*)d_in[6];
    const float* W2    = (const float*)d_in[7];
    const float* b2    = (const float*)d_in[8];
    const int*   mids  = (const int*)d_in[9];
    const int*   aids  = (const int*)d_in[10];
    const int*   dists = (const int*)d_in[11];
    const int*   gens  = (const int*)d_in[12];
    const int*   spks  = (const int*)d_in[13];

    int M = in_sizes[1];       // mention_scores has M elements
    int P = in_sizes[9];       // mention_ids has P elements
    float* out = (float*)d_out;

    fill_out_k<<<(out_size + 255) / 256, 256>>>(out, out_size);
    tables_k<<<1, 256>>>(de, ge, se, W1, b1);
    ab_k<<<(M + 7) / 8, NT>>>(g_i, W1, M);
    starts_k<<<(M + 1 + 255) / 256, 256>>>(mids, P, M);
    pair_k<<<(P + TP - 1) / TP, NT>>>(g_i, W1, W2, b2, msc,
                                      mids, aids, dists, gens, spks, P);
    softmax_k<<<(M + 7) / 8, 256>>>(out, M);
}

// round 3
// speedup vs baseline: 1.2067x; 1.2067x over previous
#include <cuda_runtime.h>

// Problem constants
#define GDIM 620
#define HH   150
#define HP   160      // H padded (pad cols exact zeros)
#define TP   128      // pairs per block
#define KC   16       // k-chunk
#define NT   256

#define MMAX 1024
#define PMAX 50176

typedef unsigned long long ull;

__device__ float d_Apad[MMAX * HP];
__device__ float d_Bpad[MMAX * HP];
__device__ float d_distT[9 * HP];
__device__ float d_genT[8 * HP];
__device__ float d_spkT[3 * HP];
__device__ float d_scores[PMAX];
__device__ int   d_starts[MMAX + 2];

// ---- packed f32x2 helpers (FFMA2; PTX-only per SASS docs). Scalar fallback
// keeps identical math/order if the toolchain lacks packed f32x2.
union U2 { ull u; float f[2]; };

__device__ __forceinline__ ull pack2(float x, float y) {
    U2 v; v.f[0] = x; v.f[1] = y; return v.u;
}
__device__ __forceinline__ void unpack2(ull v, float& x, float& y) {
    U2 t; t.u = v; x = t.f[0]; y = t.f[1];
}
__device__ __forceinline__ void fma2(ull& d, ull a, ull b) {
#if defined(__CUDA_ARCH__) && (__CUDA_ARCH__ >= 1000)
    asm("fma.rn.f32x2 %0, %1, %2, %3;" : "=l"(d) : "l"(a), "l"(b), "l"(d));
#else
    U2 dd, aa, bb; dd.u = d; aa.u = a; bb.u = b;
    dd.f[0] = fmaf(aa.f[0], bb.f[0], dd.f[0]);
    dd.f[1] = fmaf(aa.f[1], bb.f[1], dd.f[1]);
    d = dd.u;
#endif
}

// ---------------------------------------------------------------------------
// prep_k: block0 = phi tables, block1 = segment starts, blocks>=2 = output fill
// ---------------------------------------------------------------------------
__global__ void prep_k(float* __restrict__ out, int n,
                       const float* __restrict__ de, const float* __restrict__ ge,
                       const float* __restrict__ se, const float* __restrict__ W1,
                       const float* __restrict__ b1,
                       const int* __restrict__ mids, int P, int M) {
    int b = blockIdx.x;
    if (b == 0) {
        for (int e = threadIdx.x; e < 20 * HP; e += blockDim.x) {
            int row = e / HP, h = e % HP;
            const float* emb; int dbase; float* dst; float acc;
            if (row < 9)       { emb = de + row * 20;        dbase = 3 * GDIM;      dst = d_distT + row * HP + h;        acc = (h < HH) ? b1[h] : 0.0f; }
            else if (row < 17) { emb = ge + (row - 9) * 20;  dbase = 3 * GDIM + 20; dst = d_genT  + (row - 9) * HP + h;  acc = 0.0f; }
            else               { emb = se + (row - 17) * 20; dbase = 3 * GDIM + 40; dst = d_spkT  + (row - 17) * HP + h; acc = 0.0f; }
            if (h < HH) {
                #pragma unroll
                for (int k = 0; k < 20; k++) acc += emb[k] * W1[(dbase + k) * HH + h];
            }
            *dst = acc;
        }
    } else if (b == 1) {
        for (int m = threadIdx.x; m <= M; m += blockDim.x) {
            int lo = 0, hi = P;
            while (lo < hi) {
                int mid = (lo + hi) >> 1;
                if (mids[mid] < m) lo = mid + 1; else hi = mid;
            }
            d_starts[m] = lo;
        }
    } else {
        int i = (b - 2) * blockDim.x + threadIdx.x;
        if (i < n) out[i] = (i == 0) ? 1.0f : 1000.0f;
    }
}

// ---------------------------------------------------------------------------
// ab_k: A = g@W1a (blockIdx.y=0), B = g@W1b (blockIdx.y=1). 8 mentions/block,
// mention dim packed into f32x2 (4 packed accs/thread), 160 threads = h lanes.
// ---------------------------------------------------------------------------
#define ABT 160
__global__ __launch_bounds__(ABT) void ab_k(const float* __restrict__ g,
                                            const float* __restrict__ W1, int M) {
    __shared__ float gs[GDIM][10];   // [d][mention], pad to 10 (8B-aligned pairs)
    const int m0 = blockIdx.x * 8;
    const int which = blockIdx.y;
    const int tid = threadIdx.x;

    for (int e = tid; e < 8 * GDIM; e += ABT) {
        int mm = e / GDIM, d = e % GDIM;   // consecutive tid -> consecutive d: coalesced
        int m = m0 + mm;
        gs[d][mm] = (m < M) ? g[m * GDIM + d] : 0.0f;
    }
    __syncthreads();

    const int h = tid;                      // 0..159
    ull acc[4] = {0ull, 0ull, 0ull, 0ull};  // (0.0f,0.0f) pairs
    if (h < HH) {
        const float* w = W1 + (which ? GDIM * HH : 0) + h;
        #pragma unroll 4
        for (int d = 0; d < GDIM; d++) {
            float wv = __ldg(&w[d * HH]);
            ull wp = pack2(wv, wv);
            const ull* grow = (const ull*)&gs[d][0];
            fma2(acc[0], grow[0], wp);
            fma2(acc[1], grow[1], wp);
            fma2(acc[2], grow[2], wp);
            fma2(acc[3], grow[3], wp);
        }
    }
    float* dst = which ? d_Bpad : d_Apad;
    #pragma unroll
    for (int r = 0; r < 4; r++) {
        float x, y; unpack2(acc[r], x, y);
        int m = m0 + 2 * r;
        if (m < M)     dst[m * HP + h] = x;
        if (m + 1 < M) dst[(m + 1) * HP + h] = y;
    }
}

// ---------------------------------------------------------------------------
// pair_k: 128 pairs x 160 h per block; 256 threads = 16 pair-groups x 16 h-lanes.
// Per thread: 8 pairs x 5 packed h-pairs, fma.rn.f32x2 mainloop.
// ---------------------------------------------------------------------------
__global__ __launch_bounds__(NT) void pair_k(
    const float* __restrict__ g,   const float* __restrict__ W1,
    const float* __restrict__ W2,  const float* __restrict__ b2,
    const float* __restrict__ ms,
    const int* __restrict__ mids,  const int* __restrict__ aids,
    const int* __restrict__ dists, const int* __restrict__ gens,
    const int* __restrict__ spks,  int P)
{
    __shared__ int   si[TP], sj[TP], sd[TP], sg[TP], ss[TP];
    __shared__ float Xs[KC][TP + 4];    // stride 132 (float4-aligned)
    __shared__ float Ws[KC][HP];
    __shared__ float w2s[HP];

    const int tid = threadIdx.x;
    const int pb  = blockIdx.x * TP;

    if (tid < TP) {
        int p  = pb + tid;
        int ok = (p < P);
        si[tid] = ok ? mids[p] : 0;
        sj[tid] = ok ? aids[p] : 0;
        int dd  = ok ? dists[p] : 0;
        sd[tid] = (dd >= 1) + (dd >= 2) + (dd >= 3) + (dd >= 4) +
                  (dd >= 8) + (dd >= 16) + (dd >= 32) + (dd >= 64);
        sg[tid] = ok ? gens[p] : 0;
        ss[tid] = ok ? spks[p] : 0;
    }
    if (tid < HP) w2s[tid] = (tid < HH) ? W2[tid] : 0.0f;
    __syncthreads();

    const int px = tid >> 4;      // pair group
    const int hx = tid & 15;      // h lane; owns h-pairs (2hx+32q, 2hx+32q+1)
    const int p0 = px * 8;

    ull acc[8][5];
    #pragma unroll
    for (int r = 0; r < 8; r++) {
        int pp = p0 + r;
        const float2* Ap = (const float2*)&d_Apad[si[pp] * HP];
        const float2* Bp = (const float2*)&d_Bpad[sj[pp] * HP];
        const float2* Dp = (const float2*)&d_distT[sd[pp] * HP];
        const float2* Gp = (const float2*)&d_genT[sg[pp] * HP];
        const float2* Sp = (const float2*)&d_spkT[ss[pp] * HP];
        #pragma unroll
        for (int q = 0; q < 5; q++) {
            int c = hx + 16 * q;   // float2 index; h0 = 2c
            float2 a = Ap[c], b = Bp[c], d2 = Dp[c], g2 = Gp[c], s2 = Sp[c];
            acc[r][q] = pack2(a.x + b.x + d2.x + g2.x + s2.x,
                              a.y + b.y + d2.y + g2.y + s2.y);
        }
    }

    const float* W1c = W1 + (2 * GDIM) * HH;

    #pragma unroll 1
    for (int ko = 0; ko < GDIM; ko += KC) {
        __syncthreads();
        // Xs[k][p] = g[i_p][ko+k] * g[j_p][ko+k]  (2048 elems, 8/thread, coalesced 64B)
        #pragma unroll
        for (int it = 0; it < (KC * TP) / NT; it++) {
            int e  = tid + NT * it;
            int pp = e >> 4, k = e & 15;
            int kk = ko + k;
            float v = 0.0f;
            if (kk < GDIM)
                v = __ldg(&g[si[pp] * GDIM + kk]) * __ldg(&g[sj[pp] * GDIM + kk]);
            Xs[k][pp] = v;
        }
        // Ws[k][h] = W1c[(ko+k)*HH + h]  (2560 elems, 10/thread)
        #pragma unroll
        for (int it = 0; it < (KC * HP) / NT; it++) {
            int e = tid + NT * it;
            int k = e / HP, hh = e % HP;
            int kk = ko + k;
            float v = 0.0f;
            if (kk < GDIM && hh < HH) v = __ldg(&W1c[kk * HH + hh]);
            Ws[k][hh] = v;
        }
        __syncthreads();

        #pragma unroll
        for (int k = 0; k < KC; k++) {
            float4 xa = *(const float4*)&Xs[k][p0];
            float4 xb = *(const float4*)&Xs[k][p0 + 4];
            ull xp[8];
            xp[0] = pack2(xa.x, xa.x); xp[1] = pack2(xa.y, xa.y);
            xp[2] = pack2(xa.z, xa.z); xp[3] = pack2(xa.w, xa.w);
            xp[4] = pack2(xb.x, xb.x); xp[5] = pack2(xb.y, xb.y);
            xp[6] = pack2(xb.z, xb.z); xp[7] = pack2(xb.w, xb.w);
            const ull* wrow = (const ull*)&Ws[k][0];
            ull w[5];
            #pragma unroll
            for (int q = 0; q < 5; q++) w[q] = wrow[hx + 16 * q];
            #pragma unroll
            for (int r = 0; r < 8; r++)
                #pragma unroll
                for (int q = 0; q < 5; q++)
                    fma2(acc[r][q], xp[r], w[q]);
        }
    }

    // Epilogue: relu + dot(W2) + shfl-reduce over 16 h-lanes
    float b2v = __ldg(b2);
    #pragma unroll
    for (int r = 0; r < 8; r++) {
        float s = 0.0f;
        #pragma unroll
        for (int q = 0; q < 5; q++) {
            float x, y; unpack2(acc[r][q], x, y);
            int h0 = 2 * hx + 32 * q;
            x = x > 0.0f ? x : 0.0f;
            y = y > 0.0f ? y : 0.0f;
            s = fmaf(x, w2s[h0], s);
            s = fmaf(y, w2s[h0 + 1], s);
        }
        #pragma unroll
        for (int off = 8; off >= 1; off >>= 1)
            s += __shfl_xor_sync(0xffffffffu, s, off);
        if (hx == 0) {
            int p = pb + p0 + r;
            if (p < P)
                d_scores[p] = s + ms[si[p0 + r]] + ms[sj[p0 + r]] + b2v;
        }
    }
}

// ---------------------------------------------------------------------------
// Ragged softmax (+epsilon logit 0), one warp per mention
// ---------------------------------------------------------------------------
__global__ void softmax_k(float* __restrict__ out, int M) {
    int warp = (blockIdx.x * blockDim.x + threadIdx.x) >> 5;
    int lane = threadIdx.x & 31;
    if (warp >= M) return;
    int s0 = d_starts[warp], s1 = d_starts[warp + 1];
    int n = s1 - s0;

    float mx = 0.0f;
    for (int i = lane; i < n; i += 32) mx = fmaxf(mx, d_scores[s0 + i]);
    #pragma unroll
    for (int off = 16; off; off >>= 1) mx = fmaxf(mx, __shfl_xor_sync(0xffffffffu, mx, off));

    float sum = 0.0f;
    for (int i = lane; i < n; i += 32) sum += expf(d_scores[s0 + i] - mx);
    #pragma unroll
    for (int off = 16; off; off >>= 1) sum += __shfl_xor_sync(0xffffffffu, sum, off);

    float eps = expf(-mx);
    float inv = 1.0f / (sum + eps);
    float* row = out + (warp + 1) * 161;
    for (int i = lane; i < n; i += 32) row[i] = expf(d_scores[s0 + i] - mx) * inv;
    if (lane == 0) row[n] = eps * inv;
}

// ---------------------------------------------------------------------------
extern "C" void kernel_launch(void* const* d_in, const int* in_sizes, int n_in,
                              void* d_out, int out_size) {
    const float* g_i   = (const float*)d_in[0];
    const float* msc   = (const float*)d_in[1];
    const float* de    = (const float*)d_in[2];
    const float* ge    = (const float*)d_in[3];
    const float* se    = (const float*)d_in[4];
    const float* W1    = (const float*)d_in[5];
    const float* b1    = (const float*)d_in[6];
    const float* W2    = (const float*)d_in[7];
    const float* b2    = (const float*)d_in[8];
    const int*   mids  = (const int*)d_in[9];
    const int*   aids  = (const int*)d_in[10];
    const int*   dists = (const int*)d_in[11];
    const int*   gens  = (const int*)d_in[12];
    const int*   spks  = (const int*)d_in[13];

    int M = in_sizes[1];
    int P = in_sizes[9];
    float* out = (float*)d_out;

    prep_k<<<2 + (out_size + 255) / 256, 256>>>(out, out_size, de, ge, se, W1, b1, mids, P, M);
    ab_k<<<dim3((M + 7) / 8, 2), ABT>>>(g_i, W1, M);
    pair_k<<<(P + TP - 1) / TP, NT>>>(g_i, W1, W2, b2, msc,
                                      mids, aids, dists, gens, spks, P);
    softmax_k<<<(M + 7) / 8, 256>>>(out, M);
}

// round 5
// speedup vs baseline: 2.1981x; 1.8215x over previous
#include <cuda_runtime.h>

typedef unsigned int u32;
typedef unsigned long long ull;

#define GDIM 620
#define HH   150
#define HP   160
#define TP   128      // pairs per block (M tile)
#define KC   16       // K per chunk
#define NCHK 39       // ceil(620/16)
#define NT   256      // 8 warps

#define MMAX 1024
#define PMAX 50176

#define XSTR 136      // Xs row stride (floats): (l&3)*136 -> banks 8k, conflict-free frags
#define WSTR 168      // Ws/Ci row stride

__device__ float d_Apad[MMAX * HP];
__device__ float d_Bpad[MMAX * HP];
__device__ float d_distT[9 * HP];     // includes b1
__device__ float d_genT[8 * HP];
__device__ float d_spkT[3 * HP];
__device__ float d_scores[PMAX];
__device__ int   d_starts[MMAX + 2];

// ---- f32x2 helpers for ab_k (compiled fine in R3) ----
union U2 { ull u; float f[2]; };
__device__ __forceinline__ ull pack2(float x, float y) { U2 v; v.f[0]=x; v.f[1]=y; return v.u; }
__device__ __forceinline__ void unpack2(ull v, float& x, float& y) { U2 t; t.u=v; x=t.f[0]; y=t.f[1]; }
__device__ __forceinline__ void fma2(ull& d, ull a, ull b) {
#if defined(__CUDA_ARCH__) && (__CUDA_ARCH__ >= 1000)
    asm("fma.rn.f32x2 %0, %1, %2, %3;" : "=l"(d) : "l"(a), "l"(b), "l"(d));
#else
    U2 dd,aa,bb; dd.u=d; aa.u=a; bb.u=b;
    dd.f[0]=fmaf(aa.f[0],bb.f[0],dd.f[0]); dd.f[1]=fmaf(aa.f[1],bb.f[1],dd.f[1]); d=dd.u;
#endif
}

__device__ __forceinline__ float totf32(float x) {
    u32 u; asm("cvt.rna.tf32.f32 %0, %1;" : "=r"(u) : "f"(x));
    return __uint_as_float(u);
}

#define MMA_TF32(C, A, B0, B1)                                              \
    asm volatile("mma.sync.aligned.m16n8k8.row.col.f32.tf32.tf32.f32 "      \
        "{%0,%1,%2,%3}, {%4,%5,%6,%7}, {%8,%9}, {%0,%1,%2,%3};"             \
        : "+f"((C)[0]), "+f"((C)[1]), "+f"((C)[2]), "+f"((C)[3])            \
        : "r"((A)[0]), "r"((A)[1]), "r"((A)[2]), "r"((A)[3]),               \
          "r"(B0), "r"(B1))

// ---- shared layout (bytes) ----
#define SM_SI   0
#define SM_SJ   512
#define SM_DB   1024
#define SM_GN   1536
#define SM_SP   2048
#define SM_W2   2560
#define SM_SRED 3200                      // 128*2 floats
#define SM_CI   4224                      // 128*168*4 = 86016
#define SM_XS   (4224 + 86016)            // 2*16*136*4 = 17408
#define SM_WS   (SM_XS + 17408)           // 2*16*168*4 = 21504
#define SM_TOT  (SM_WS + 21504)           // 129152

// ---------------------------------------------------------------------------
// prep_k: block0 phi tables (+b1 folded into distT), block1 starts, rest fill
// ---------------------------------------------------------------------------
__global__ void prep_k(float* __restrict__ out, int n,
                       const float* __restrict__ de, const float* __restrict__ ge,
                       const float* __restrict__ se, const float* __restrict__ W1,
                       const float* __restrict__ b1,
                       const int* __restrict__ mids, int P, int M) {
    int b = blockIdx.x;
    if (b == 0) {
        for (int e = threadIdx.x; e < 20 * HP; e += blockDim.x) {
            int row = e / HP, h = e % HP;
            const float* emb; int dbase; float* dst; float acc;
            if (row < 9)       { emb = de + row * 20;        dbase = 3 * GDIM;      dst = d_distT + row * HP + h;        acc = (h < HH) ? b1[h] : 0.0f; }
            else if (row < 17) { emb = ge + (row - 9) * 20;  dbase = 3 * GDIM + 20; dst = d_genT  + (row - 9) * HP + h;  acc = 0.0f; }
            else               { emb = se + (row - 17) * 20; dbase = 3 * GDIM + 40; dst = d_spkT  + (row - 17) * HP + h; acc = 0.0f; }
            if (h < HH) {
                #pragma unroll
                for (int k = 0; k < 20; k++) acc += emb[k] * W1[(dbase + k) * HH + h];
            }
            *dst = acc;
        }
    } else if (b == 1) {
        for (int m = threadIdx.x; m <= M; m += blockDim.x) {
            int lo = 0, hi = P;
            while (lo < hi) {
                int mid = (lo + hi) >> 1;
                if (mids[mid] < m) lo = mid + 1; else hi = mid;
            }
            d_starts[m] = lo;
        }
    } else {
        int i = (b - 2) * blockDim.x + threadIdx.x;
        if (i < n) out[i] = (i == 0) ? 1.0f : 1000.0f;
    }
}

// ---------------------------------------------------------------------------
// ab_k: A = g@W1a (y=0), B = g@W1b (y=1). 8 mentions/block, f32x2 accs.
// ---------------------------------------------------------------------------
#define ABT 160
__global__ __launch_bounds__(ABT) void ab_k(const float* __restrict__ g,
                                            const float* __restrict__ W1, int M) {
    __shared__ float gs[GDIM][10];
    const int m0 = blockIdx.x * 8;
    const int which = blockIdx.y;
    const int tid = threadIdx.x;

    for (int e = tid; e < 8 * GDIM; e += ABT) {
        int mm = e / GDIM, d = e % GDIM;
        int m = m0 + mm;
        gs[d][mm] = (m < M) ? g[m * GDIM + d] : 0.0f;
    }
    __syncthreads();

    const int h = tid;
    ull acc[4] = {0ull, 0ull, 0ull, 0ull};
    if (h < HH) {
        const float* w = W1 + (which ? GDIM * HH : 0) + h;
        #pragma unroll 4
        for (int d = 0; d < GDIM; d++) {
            float wv = __ldg(&w[d * HH]);
            ull wp = pack2(wv, wv);
            const ull* grow = (const ull*)&gs[d][0];
            fma2(acc[0], grow[0], wp);
            fma2(acc[1], grow[1], wp);
            fma2(acc[2], grow[2], wp);
            fma2(acc[3], grow[3], wp);
        }
    }
    float* dst = which ? d_Bpad : d_Apad;
    #pragma unroll
    for (int r = 0; r < 4; r++) {
        float x, y; unpack2(acc[r], x, y);
        int m = m0 + 2 * r;
        if (m < M)     dst[m * HP + h] = x;
        if (m + 1 < M) dst[(m + 1) * HP + h] = y;
    }
}

// ---------------------------------------------------------------------------
// pair_k: per block 128 pairs x 160 h. C init = A[i]+B[j]+phi (exact fp32),
// then tf32 mma.sync over the Hadamard GEMM (K=620, 39 chunks, double-buffered
// smem with register prefetch). Epilogue: relu + dot(W2) + mention scores.
// 8 warps: warp w -> m-block (w&3)*32 rows, n-block (w>>2)*80 cols.
// ---------------------------------------------------------------------------
__global__ __launch_bounds__(NT) void pair_k(
    const float* __restrict__ g,   const float* __restrict__ W1,
    const float* __restrict__ W2,  const float* __restrict__ b2,
    const float* __restrict__ ms,
    const int* __restrict__ mids,  const int* __restrict__ aids,
    const int* __restrict__ dists, const int* __restrict__ gens,
    const int* __restrict__ spks,  int P)
{
    extern __shared__ char smc[];
    int*   s_si = (int*)(smc + SM_SI);
    int*   s_sj = (int*)(smc + SM_SJ);
    int*   s_db = (int*)(smc + SM_DB);
    int*   s_gn = (int*)(smc + SM_GN);
    int*   s_sp = (int*)(smc + SM_SP);
    float* w2s  = (float*)(smc + SM_W2);
    float* sred = (float*)(smc + SM_SRED);
    float* Ci   = (float*)(smc + SM_CI);
    float* Xs   = (float*)(smc + SM_XS);
    float* Ws   = (float*)(smc + SM_WS);

    const int tid = threadIdx.x;
    const int pb  = blockIdx.x * TP;

    if (tid < TP) {
        int p = pb + tid;
        bool ok = p < P;
        s_si[tid] = ok ? mids[p] : 0;
        s_sj[tid] = ok ? aids[p] : 0;
        int dd = ok ? dists[p] : 0;
        s_db[tid] = (dd >= 1) + (dd >= 2) + (dd >= 3) + (dd >= 4) +
                    (dd >= 8) + (dd >= 16) + (dd >= 32) + (dd >= 64);
        s_gn[tid] = ok ? gens[p] : 0;
        s_sp[tid] = ok ? spks[p] : 0;
    }
    if (tid < HP) w2s[tid] = (tid < HH) ? W2[tid] : 0.0f;
    __syncthreads();

    // ---- build exact init tile Ci[128][160] (stride WSTR), float4 path
    {
        const float4* A4 = (const float4*)d_Apad;
        const float4* B4 = (const float4*)d_Bpad;
        const float4* D4 = (const float4*)d_distT;
        const float4* G4 = (const float4*)d_genT;
        const float4* S4 = (const float4*)d_spkT;
        #pragma unroll
        for (int it = 0; it < (TP * 40) / NT; it++) {
            int e = tid + NT * it;
            int row = e / 40, c4 = e % 40;
            float4 a = __ldg(&A4[s_si[row] * 40 + c4]);
            float4 b = __ldg(&B4[s_sj[row] * 40 + c4]);
            float4 d = __ldg(&D4[s_db[row] * 40 + c4]);
            float4 gg = __ldg(&G4[s_gn[row] * 40 + c4]);
            float4 s = __ldg(&S4[s_sp[row] * 40 + c4]);
            float4 v = make_float4(a.x+b.x+d.x+gg.x+s.x, a.y+b.y+d.y+gg.y+s.y,
                                   a.z+b.z+d.z+gg.z+s.z, a.w+b.w+d.w+gg.w+s.w);
            *(float4*)(Ci + row * WSTR + c4 * 4) = v;
        }
    }
    __syncthreads();

    const int lid = tid & 31, wi = tid >> 5;
    const int mBlk = (wi & 3) * 32, nBlk = (wi >> 2) * 80;
    const int tig = lid & 3, grp = lid >> 2;

    // ---- load C fragments from Ci
    float c[2][10][4];
    #pragma unroll
    for (int ma = 0; ma < 2; ma++) {
        int r = mBlk + ma * 16 + grp;
        #pragma unroll
        for (int na = 0; na < 10; na++) {
            int col = nBlk + na * 8 + 2 * tig;
            float2 lo = *(const float2*)(Ci + r * WSTR + col);
            float2 hi = *(const float2*)(Ci + (r + 8) * WSTR + col);
            c[ma][na][0] = lo.x; c[ma][na][1] = lo.y;
            c[ma][na][2] = hi.x; c[ma][na][3] = hi.y;
        }
    }

    // ---- prefetch pointers for X fill (8 elems/thread: pp = e>>4, k = e&15)
    const float* W1c = W1 + (2 * GDIM) * HH;
    const float* pi[8]; const float* pj[8];
    #pragma unroll
    for (int it = 0; it < 8; it++) {
        int pp = (tid + NT * it) >> 4;
        pi[it] = g + s_si[pp] * GDIM;
        pj[it] = g + s_sj[pp] * GDIM;
    }

    float xv[8], wv[10];
    // load chunk 0
    {
        #pragma unroll
        for (int it = 0; it < 8; it++) {
            int k = (tid + NT * it) & 15;
            xv[it] = __ldg(pi[it] + k) * __ldg(pj[it] + k);
        }
        #pragma unroll
        for (int it = 0; it < 10; it++) {
            int e = tid + NT * it, k = e / HP, h = e % HP;
            wv[it] = (h < HH) ? __ldg(&W1c[k * HH + h]) : 0.0f;
        }
    }

    for (int cch = 0; cch < NCHK; cch++) {
        const int buf = cch & 1;
        float* Xb = Xs + buf * (KC * XSTR);
        float* Wb = Ws + buf * (KC * WSTR);

        // store prefetched chunk (tf32-converted)
        #pragma unroll
        for (int it = 0; it < 8; it++) {
            int e = tid + NT * it;
            Xb[(e & 15) * XSTR + (e >> 4)] = totf32(xv[it]);
        }
        #pragma unroll
        for (int it = 0; it < 10; it++) {
            int e = tid + NT * it;
            Wb[(e / HP) * WSTR + (e % HP)] = totf32(wv[it]);
        }
        __syncthreads();

        // issue next chunk's loads (hidden under mma)
        if (cch + 1 < NCHK) {
            int k0n = (cch + 1) * KC;
            #pragma unroll
            for (int it = 0; it < 8; it++) {
                int kk = k0n + ((tid + NT * it) & 15);
                xv[it] = (kk < GDIM) ? __ldg(pi[it] + kk) * __ldg(pj[it] + kk) : 0.0f;
            }
            #pragma unroll
            for (int it = 0; it < 10; it++) {
                int e = tid + NT * it, k = e / HP, h = e % HP;
                int kk = k0n + k;
                wv[it] = (kk < GDIM && h < HH) ? __ldg(&W1c[kk * HH + h]) : 0.0f;
            }
        }

        // compute: 2 k8 steps x (2 m-atoms x 10 n-atoms) mma
        #pragma unroll
        for (int s = 0; s < 2; s++) {
            int kb = (8 * s + tig);
            u32 a[2][4];
            #pragma unroll
            for (int ma = 0; ma < 2; ma++) {
                int r = mBlk + ma * 16 + grp;
                a[ma][0] = __float_as_uint(Xb[kb * XSTR + r]);
                a[ma][1] = __float_as_uint(Xb[kb * XSTR + r + 8]);
                a[ma][2] = __float_as_uint(Xb[(kb + 4) * XSTR + r]);
                a[ma][3] = __float_as_uint(Xb[(kb + 4) * XSTR + r + 8]);
            }
            #pragma unroll
            for (int na = 0; na < 10; na++) {
                int col = nBlk + na * 8 + grp;
                u32 b0 = __float_as_uint(Wb[kb * WSTR + col]);
                u32 b1r = __float_as_uint(Wb[(kb + 4) * WSTR + col]);
                MMA_TF32(c[0][na], a[0], b0, b1r);
                MMA_TF32(c[1][na], a[1], b0, b1r);
            }
        }
        __syncthreads();
    }

    // ---- epilogue: relu + dot W2, reduce 4 lanes (tig group), combine n-blocks
    float part[2][2] = {{0.f, 0.f}, {0.f, 0.f}};
    #pragma unroll
    for (int ma = 0; ma < 2; ma++)
        #pragma unroll
        for (int na = 0; na < 10; na++) {
            int col = nBlk + na * 8 + 2 * tig;
            float w0 = w2s[col], w1 = w2s[col + 1];
            float v0 = fmaxf(c[ma][na][0], 0.f), v1 = fmaxf(c[ma][na][1], 0.f);
            float v2 = fmaxf(c[ma][na][2], 0.f), v3 = fmaxf(c[ma][na][3], 0.f);
            part[ma][0] += v0 * w0 + v1 * w1;
            part[ma][1] += v2 * w0 + v3 * w1;
        }
    #pragma unroll
    for (int ma = 0; ma < 2; ma++)
        #pragma unroll
        for (int rr = 0; rr < 2; rr++) {
            float v = part[ma][rr];
            v += __shfl_xor_sync(0xffffffffu, v, 1);
            v += __shfl_xor_sync(0xffffffffu, v, 2);
            part[ma][rr] = v;
        }
    if (tig == 0) {
        int nb = wi >> 2;
        #pragma unroll
        for (int ma = 0; ma < 2; ma++)
            #pragma unroll
            for (int rr = 0; rr < 2; rr++) {
                int row = mBlk + ma * 16 + grp + 8 * rr;
                sred[row * 2 + nb] = part[ma][rr];
            }
    }
    __syncthreads();
    if (tid < TP) {
        int p = pb + tid;
        if (p < P) {
            float s = sred[tid * 2] + sred[tid * 2 + 1];
            d_scores[p] = s + __ldg(b2) + ms[s_si[tid]] + ms[s_sj[tid]];
        }
    }
}

// ---------------------------------------------------------------------------
// Ragged softmax (+epsilon logit 0), one warp per mention
// ---------------------------------------------------------------------------
__global__ void softmax_k(float* __restrict__ out, int M) {
    int warp = (blockIdx.x * blockDim.x + threadIdx.x) >> 5;
    int lane = threadIdx.x & 31;
    if (warp >= M) return;
    int s0 = d_starts[warp], s1 = d_starts[warp + 1];
    int n = s1 - s0;

    float mx = 0.0f;
    for (int i = lane; i < n; i += 32) mx = fmaxf(mx, d_scores[s0 + i]);
    #pragma unroll
    for (int off = 16; off; off >>= 1) mx = fmaxf(mx, __shfl_xor_sync(0xffffffffu, mx, off));

    float sum = 0.0f;
    for (int i = lane; i < n; i += 32) sum += expf(d_scores[s0 + i] - mx);
    #pragma unroll
    for (int off = 16; off; off >>= 1) sum += __shfl_xor_sync(0xffffffffu, sum, off);

    float eps = expf(-mx);
    float inv = 1.0f / (sum + eps);
    float* row = out + (warp + 1) * 161;
    for (int i = lane; i < n; i += 32) row[i] = expf(d_scores[s0 + i] - mx) * inv;
    if (lane == 0) row[n] = eps * inv;
}

// ---------------------------------------------------------------------------
extern "C" void kernel_launch(void* const* d_in, const int* in_sizes, int n_in,
                              void* d_out, int out_size) {
    const float* g_i   = (const float*)d_in[0];
    const float* msc   = (const float*)d_in[1];
    const float* de    = (const float*)d_in[2];
    const float* ge    = (const float*)d_in[3];
    const float* se    = (const float*)d_in[4];
    const float* W1    = (const float*)d_in[5];
    const float* b1    = (const float*)d_in[6];
    const float* W2    = (const float*)d_in[7];
    const float* b2    = (const float*)d_in[8];
    const int*   mids  = (const int*)d_in[9];
    const int*   aids  = (const int*)d_in[10];
    const int*   dists = (const int*)d_in[11];
    const int*   gens  = (const int*)d_in[12];
    const int*   spks  = (const int*)d_in[13];

    int M = in_sizes[1];
    int P = in_sizes[9];
    float* out = (float*)d_out;

    static int attr_done = 0;
    if (!attr_done) {
        cudaFuncSetAttribute(pair_k, cudaFuncAttributeMaxDynamicSharedMemorySize, SM_TOT);
        attr_done = 1;
    }

    prep_k<<<2 + (out_size + 255) / 256, 256>>>(out, out_size, de, ge, se, W1, b1, mids, P, M);
    ab_k<<<dim3((M + 7) / 8, 2), ABT>>>(g_i, W1, M);
    pair_k<<<(P + TP - 1) / TP, NT, SM_TOT>>>(g_i, W1, W2, b2, msc,
                                              mids, aids, dists, gens, spks, P);
    softmax_k<<<(M + 7) / 8, 256>>>(out, M);
}

// round 6
// speedup vs baseline: 3.1483x; 1.4323x over previous
#include <cuda_runtime.h>
#include <cuda_fp16.h>

typedef unsigned int u32;
typedef unsigned long long ull;

#define GDIM 620
#define HH   150
#define HP   160
#define TP   128      // pairs per block (M tile)
#define KC   32       // K per chunk (2 x k16 mma steps)
#define NCHK 20       // ceil(620/32)
#define NT   256      // 8 warps

#define MMAX 1024
#define PMAX 50176

#define XH   40       // Xs/Ws row stride in halfs (20 words -> conflict-free frags)
#define CST  168      // Ci row stride in floats

__device__ float  d_Apad[MMAX * HP];
__device__ float  d_Bpad[MMAX * HP];
__device__ float  d_distT[9 * HP];     // includes b1
__device__ float  d_genT[8 * HP];
__device__ float  d_spkT[3 * HP];
__device__ __half d_WtH[HP * 640];     // W1c^T fp16, [h][k] padded (zeros outside)
__device__ float  d_scores[PMAX];
__device__ int    d_starts[MMAX + 2];

// ---- f32x2 helpers for ab_k ----
union U2 { ull u; float f[2]; };
__device__ __forceinline__ ull pack2(float x, float y) { U2 v; v.f[0]=x; v.f[1]=y; return v.u; }
__device__ __forceinline__ void unpack2(ull v, float& x, float& y) { U2 t; t.u=v; x=t.f[0]; y=t.f[1]; }
__device__ __forceinline__ void fma2(ull& d, ull a, ull b) {
#if defined(__CUDA_ARCH__) && (__CUDA_ARCH__ >= 1000)
    asm("fma.rn.f32x2 %0, %1, %2, %3;" : "=l"(d) : "l"(a), "l"(b), "l"(d));
#else
    U2 dd,aa,bb; dd.u=d; aa.u=a; bb.u=b;
    dd.f[0]=fmaf(aa.f[0],bb.f[0],dd.f[0]); dd.f[1]=fmaf(aa.f[1],bb.f[1],dd.f[1]); d=dd.u;
#endif
}

#define MMA_F16(C, A, B0, B1)                                               \
    asm volatile("mma.sync.aligned.m16n8k16.row.col.f32.f16.f16.f32 "       \
        "{%0,%1,%2,%3}, {%4,%5,%6,%7}, {%8,%9}, {%0,%1,%2,%3};"             \
        : "+f"((C)[0]), "+f"((C)[1]), "+f"((C)[2]), "+f"((C)[3])            \
        : "r"((A)[0]), "r"((A)[1]), "r"((A)[2]), "r"((A)[3]),               \
          "r"(B0), "r"(B1))

// ---- shared layout (bytes). BIG region: Ci (init phase) aliases Xs+Ws (mainloop)
#define SM_SI   0
#define SM_SJ   512
#define SM_DB   1024
#define SM_GN   1536
#define SM_SP   2048
#define SM_W2   2560
#define SM_SRED 3200                   // 128*2 floats
#define SM_BIG  4224
#define CI_BYTES (TP * CST * 4)        // 86016
#define XS_OFF  SM_BIG                 // halfs: 128*40*2 = 10240
#define WS_OFF  (SM_BIG + TP * XH * 2) // halfs: 160*40*2 = 12800
#define SM_TOT  (SM_BIG + CI_BYTES)    // 90240 -> 2 CTAs/SM

// ---------------------------------------------------------------------------
// prep_k: block0 phi tables (+b1 folded into distT), block1 starts, rest fill
// ---------------------------------------------------------------------------
__global__ void prep_k(float* __restrict__ out, int n,
                       const float* __restrict__ de, const float* __restrict__ ge,
                       const float* __restrict__ se, const float* __restrict__ W1,
                       const float* __restrict__ b1,
                       const int* __restrict__ mids, int P, int M) {
    int b = blockIdx.x;
    if (b == 0) {
        for (int e = threadIdx.x; e < 20 * HP; e += blockDim.x) {
            int row = e / HP, h = e % HP;
            const float* emb; int dbase; float* dst; float acc;
            if (row < 9)       { emb = de + row * 20;        dbase = 3 * GDIM;      dst = d_distT + row * HP + h;        acc = (h < HH) ? b1[h] : 0.0f; }
            else if (row < 17) { emb = ge + (row - 9) * 20;  dbase = 3 * GDIM + 20; dst = d_genT  + (row - 9) * HP + h;  acc = 0.0f; }
            else               { emb = se + (row - 17) * 20; dbase = 3 * GDIM + 40; dst = d_spkT  + (row - 17) * HP + h; acc = 0.0f; }
            if (h < HH) {
                #pragma unroll
                for (int k = 0; k < 20; k++) acc += emb[k] * W1[(dbase + k) * HH + h];
            }
            *dst = acc;
        }
    } else if (b == 1) {
        for (int m = threadIdx.x; m <= M; m += blockDim.x) {
            int lo = 0, hi = P;
            while (lo < hi) {
                int mid = (lo + hi) >> 1;
                if (mids[mid] < m) lo = mid + 1; else hi = mid;
            }
            d_starts[m] = lo;
        }
    } else {
        int i = (b - 2) * blockDim.x + threadIdx.x;
        if (i < n) out[i] = (i == 0) ? 1.0f : 1000.0f;
    }
}

// ---------------------------------------------------------------------------
// wth_k: W1c^T -> fp16 [160][640], zero-padded (h>=150 or k>=620)
// ---------------------------------------------------------------------------
__global__ void wth_k(const float* __restrict__ W1) {
    int idx = blockIdx.x * 256 + threadIdx.x;
    if (idx >= HP * 640) return;
    int h = idx / 640, k = idx % 640;
    const float* W1c = W1 + 2 * GDIM * HH;
    float v = (h < HH && k < GDIM) ? W1c[k * HH + h] : 0.0f;
    d_WtH[idx] = __float2half(v);
}

// ---------------------------------------------------------------------------
// ab_k: A = g@W1a (y=0), B = g@W1b (y=1). 8 mentions/block, f32x2 accs.
// ---------------------------------------------------------------------------
#define ABT 160
__global__ __launch_bounds__(ABT) void ab_k(const float* __restrict__ g,
                                            const float* __restrict__ W1, int M) {
    __shared__ float gs[GDIM][10];
    const int m0 = blockIdx.x * 8;
    const int which = blockIdx.y;
    const int tid = threadIdx.x;

    for (int e = tid; e < 8 * GDIM; e += ABT) {
        int mm = e / GDIM, d = e % GDIM;
        int m = m0 + mm;
        gs[d][mm] = (m < M) ? g[m * GDIM + d] : 0.0f;
    }
    __syncthreads();

    const int h = tid;
    ull acc[4] = {0ull, 0ull, 0ull, 0ull};
    if (h < HH) {
        const float* w = W1 + (which ? GDIM * HH : 0) + h;
        #pragma unroll 4
        for (int d = 0; d < GDIM; d++) {
            float wv = __ldg(&w[d * HH]);
            ull wp = pack2(wv, wv);
            const ull* grow = (const ull*)&gs[d][0];
            fma2(acc[0], grow[0], wp);
            fma2(acc[1], grow[1], wp);
            fma2(acc[2], grow[2], wp);
            fma2(acc[3], grow[3], wp);
        }
    }
    float* dst = which ? d_Bpad : d_Apad;
    #pragma unroll
    for (int r = 0; r < 4; r++) {
        float x, y; unpack2(acc[r], x, y);
        int m = m0 + 2 * r;
        if (m < M)     dst[m * HP + h] = x;
        if (m + 1 < M) dst[(m + 1) * HP + h] = y;
    }
}

// ---------------------------------------------------------------------------
// pair_k: 128 pairs x 160 h per block, 8 warps (4 m-blocks x 2 n-blocks).
// C init exact fp32 (A[i]+B[j]+phi via smem Ci, aliased with Xs/Ws);
// Hadamard GEMM in fp16 m16n8k16 with fp32 accum. 2 CTAs/SM.
// ---------------------------------------------------------------------------
__global__ __launch_bounds__(NT, 2) void pair_k(
    const float* __restrict__ g,   const float* __restrict__ W2,
    const float* __restrict__ b2,  const float* __restrict__ ms,
    const int* __restrict__ mids,  const int* __restrict__ aids,
    const int* __restrict__ dists, const int* __restrict__ gens,
    const int* __restrict__ spks,  int P)
{
    extern __shared__ char smc[];
    int*   s_si = (int*)(smc + SM_SI);
    int*   s_sj = (int*)(smc + SM_SJ);
    int*   s_db = (int*)(smc + SM_DB);
    int*   s_gn = (int*)(smc + SM_GN);
    int*   s_sp = (int*)(smc + SM_SP);
    float* w2s  = (float*)(smc + SM_W2);
    float* sred = (float*)(smc + SM_SRED);
    float* Ci   = (float*)(smc + SM_BIG);
    __half* Xs  = (__half*)(smc + XS_OFF);
    __half* Ws  = (__half*)(smc + WS_OFF);

    const int tid = threadIdx.x;
    const int pb  = blockIdx.x * TP;

    if (tid < TP) {
        int p = pb + tid;
        bool ok = p < P;
        s_si[tid] = ok ? mids[p] : 0;
        s_sj[tid] = ok ? aids[p] : 0;
        int dd = ok ? dists[p] : 0;
        s_db[tid] = (dd >= 1) + (dd >= 2) + (dd >= 3) + (dd >= 4) +
                    (dd >= 8) + (dd >= 16) + (dd >= 32) + (dd >= 64);
        s_gn[tid] = ok ? gens[p] : 0;
        s_sp[tid] = ok ? spks[p] : 0;
    }
    if (tid < HP) w2s[tid] = (tid < HH) ? W2[tid] : 0.0f;
    __syncthreads();

    // ---- stage exact init tile Ci[128][160] (fp32, stride CST)
    {
        const float4* A4 = (const float4*)d_Apad;
        const float4* B4 = (const float4*)d_Bpad;
        const float4* D4 = (const float4*)d_distT;
        const float4* G4 = (const float4*)d_genT;
        const float4* S4 = (const float4*)d_spkT;
        #pragma unroll
        for (int it = 0; it < (TP * 40) / NT; it++) {
            int e = tid + NT * it;
            int row = e / 40, c4 = e % 40;
            float4 a = __ldg(&A4[s_si[row] * 40 + c4]);
            float4 b = __ldg(&B4[s_sj[row] * 40 + c4]);
            float4 d = __ldg(&D4[s_db[row] * 40 + c4]);
            float4 gg = __ldg(&G4[s_gn[row] * 40 + c4]);
            float4 s = __ldg(&S4[s_sp[row] * 40 + c4]);
            float4 v = make_float4(a.x+b.x+d.x+gg.x+s.x, a.y+b.y+d.y+gg.y+s.y,
                                   a.z+b.z+d.z+gg.z+s.z, a.w+b.w+d.w+gg.w+s.w);
            *(float4*)(Ci + row * CST + c4 * 4) = v;
        }
    }
    __syncthreads();

    const int lid = tid & 31, wi = tid >> 5;
    const int mBlk = (wi & 3) * 32, nBlk = (wi >> 2) * 80;
    const int tig = lid & 3, grp = lid >> 2;

    // ---- load C fragments from Ci (then Ci region is reused as Xs/Ws)
    float c[2][10][4];
    #pragma unroll
    for (int ma = 0; ma < 2; ma++) {
        int r = mBlk + ma * 16 + grp;
        #pragma unroll
        for (int na = 0; na < 10; na++) {
            int col = nBlk + na * 8 + 2 * tig;
            float2 lo = *(const float2*)(Ci + r * CST + col);
            float2 hi = *(const float2*)(Ci + (r + 8) * CST + col);
            c[ma][na][0] = lo.x; c[ma][na][1] = lo.y;
            c[ma][na][2] = hi.x; c[ma][na][3] = hi.y;
        }
    }

    // X-fill assignment: thread -> (row, 16-k half-slab)
    const int myrow = tid >> 1, par = tid & 1;
    const float4* gi4 = (const float4*)g + s_si[myrow] * 155;
    const float4* gj4 = (const float4*)g + s_sj[myrow] * 155;
    const uint4* wsrc = (const uint4*)d_WtH + tid * 80;   // row = tid (if < 160)

    const u32* Xw = (const u32*)Xs;
    const u32* Ww = (const u32*)Ws;

    for (int cch = 0; cch < NCHK; cch++) {
        __syncthreads();   // prior reads of Ci / Xs / Ws complete
        // ---- X fill: Xs[myrow][par*16 .. par*16+15] (fp16)
        {
            int k4 = cch * 8 + par * 4;
            uint4 st[2];
            __half2* h2 = (__half2*)st;
            #pragma unroll
            for (int q = 0; q < 4; q++) {
                int idx = k4 + q;
                float4 va, vb;
                if (idx < 155) { va = __ldg(gi4 + idx); vb = __ldg(gj4 + idx); }
                else { va = make_float4(0.f,0.f,0.f,0.f); vb = va; }
                h2[2*q]   = __floats2half2_rn(va.x * vb.x, va.y * vb.y);
                h2[2*q+1] = __floats2half2_rn(va.z * vb.z, va.w * vb.w);
            }
            uint4* dst = (uint4*)(Xs + myrow * XH + par * 16);
            dst[0] = st[0]; dst[1] = st[1];
        }
        // ---- W fill: Ws[h][0..31] from pre-transposed fp16 (threads 0..159)
        if (tid < HP) {
            const uint4* src = wsrc + cch * 4;
            uint4* dst = (uint4*)(Ws + tid * XH);
            dst[0] = __ldg(src + 0); dst[1] = __ldg(src + 1);
            dst[2] = __ldg(src + 2); dst[3] = __ldg(src + 3);
        }
        __syncthreads();

        // ---- mma: 2 x k16 steps
        #pragma unroll
        for (int s = 0; s < 2; s++) {
            const int kw = s * 8;   // k offset in 32-bit words
            u32 a[2][4];
            #pragma unroll
            for (int ma = 0; ma < 2; ma++) {
                int r = mBlk + ma * 16 + grp;
                a[ma][0] = Xw[r * 20 + kw + tig];
                a[ma][1] = Xw[(r + 8) * 20 + kw + tig];
                a[ma][2] = Xw[r * 20 + kw + 4 + tig];
                a[ma][3] = Xw[(r + 8) * 20 + kw + 4 + tig];
            }
            #pragma unroll
            for (int na = 0; na < 10; na++) {
                int col = nBlk + na * 8 + grp;
                u32 b0 = Ww[col * 20 + kw + tig];
                u32 b1 = Ww[col * 20 + kw + 4 + tig];
                MMA_F16(c[0][na], a[0], b0, b1);
                MMA_F16(c[1][na], a[1], b0, b1);
            }
        }
    }

    // ---- epilogue: relu + dot W2, reduce over tig, combine n-blocks via sred
    float part[2][2] = {{0.f, 0.f}, {0.f, 0.f}};
    #pragma unroll
    for (int ma = 0; ma < 2; ma++)
        #pragma unroll
        for (int na = 0; na < 10; na++) {
            int col = nBlk + na * 8 + 2 * tig;
            float w0 = w2s[col], w1 = w2s[col + 1];
            float v0 = fmaxf(c[ma][na][0], 0.f), v1 = fmaxf(c[ma][na][1], 0.f);
            float v2 = fmaxf(c[ma][na][2], 0.f), v3 = fmaxf(c[ma][na][3], 0.f);
            part[ma][0] += v0 * w0 + v1 * w1;
            part[ma][1] += v2 * w0 + v3 * w1;
        }
    #pragma unroll
    for (int ma = 0; ma < 2; ma++)
        #pragma unroll
        for (int rr = 0; rr < 2; rr++) {
            float v = part[ma][rr];
            v += __shfl_xor_sync(0xffffffffu, v, 1);
            v += __shfl_xor_sync(0xffffffffu, v, 2);
            part[ma][rr] = v;
        }
    if (tig == 0) {
        int nb = wi >> 2;
        #pragma unroll
        for (int ma = 0; ma < 2; ma++)
            #pragma unroll
            for (int rr = 0; rr < 2; rr++) {
                int row = mBlk + ma * 16 + grp + 8 * rr;
                sred[row * 2 + nb] = part[ma][rr];
            }
    }
    __syncthreads();
    if (tid < TP) {
        int p = pb + tid;
        if (p < P) {
            float s = sred[tid * 2] + sred[tid * 2 + 1];
            d_scores[p] = s + __ldg(b2) + ms[s_si[tid]] + ms[s_sj[tid]];
        }
    }
}

// ---------------------------------------------------------------------------
// Ragged softmax (+epsilon logit 0), one warp per mention
// ---------------------------------------------------------------------------
__global__ void softmax_k(float* __restrict__ out, int M) {
    int warp = (blockIdx.x * blockDim.x + threadIdx.x) >> 5;
    int lane = threadIdx.x & 31;
    if (warp >= M) return;
    int s0 = d_starts[warp], s1 = d_starts[warp + 1];
    int n = s1 - s0;

    float mx = 0.0f;
    for (int i = lane; i < n; i += 32) mx = fmaxf(mx, d_scores[s0 + i]);
    #pragma unroll
    for (int off = 16; off; off >>= 1) mx = fmaxf(mx, __shfl_xor_sync(0xffffffffu, mx, off));

    float sum = 0.0f;
    for (int i = lane; i < n; i += 32) sum += expf(d_scores[s0 + i] - mx);
    #pragma unroll
    for (int off = 16; off; off >>= 1) sum += __shfl_xor_sync(0xffffffffu, sum, off);

    float eps = expf(-mx);
    float inv = 1.0f / (sum + eps);
    float* row = out + (warp + 1) * 161;
    for (int i = lane; i < n; i += 32) row[i] = expf(d_scores[s0 + i] - mx) * inv;
    if (lane == 0) row[n] = eps * inv;
}

// ---------------------------------------------------------------------------
extern "C" void kernel_launch(void* const* d_in, const int* in_sizes, int n_in,
                              void* d_out, int out_size) {
    const float* g_i   = (const float*)d_in[0];
    const float* msc   = (const float*)d_in[1];
    const float* de    = (const float*)d_in[2];
    const float* ge    = (const float*)d_in[3];
    const float* se    = (const float*)d_in[4];
    const float* W1    = (const float*)d_in[5];
    const float* b1    = (const float*)d_in[6];
    const float* W2    = (const float*)d_in[7];
    const float* b2    = (const float*)d_in[8];
    const int*   mids  = (const int*)d_in[9];
    const int*   aids  = (const int*)d_in[10];
    const int*   dists = (const int*)d_in[11];
    const int*   gens  = (const int*)d_in[12];
    const int*   spks  = (const int*)d_in[13];

    int M = in_sizes[1];
    int P = in_sizes[9];
    float* out = (float*)d_out;

    cudaFuncSetAttribute(pair_k, cudaFuncAttributeMaxDynamicSharedMemorySize, SM_TOT);

    prep_k<<<2 + (out_size + 255) / 256, 256>>>(out, out_size, de, ge, se, W1, b1, mids, P, M);
    wth_k<<<(HP * 640 + 255) / 256, 256>>>(W1);
    ab_k<<<dim3((M + 7) / 8, 2), ABT>>>(g_i, W1, M);
    pair_k<<<(P + TP - 1) / TP, NT, SM_TOT>>>(g_i, W2, b2, msc,
                                              mids, aids, dists, gens, spks, P);
    softmax_k<<<(M + 7) / 8, 256>>>(out, M);
}

// round 8
// speedup vs baseline: 3.3045x; 1.0496x over previous
#include <cuda_runtime.h>
#include <cuda_fp16.h>

typedef unsigned int u32;
typedef unsigned long long ull;

#define GDIM 620
#define HH   150
#define HP   160
#define TP   128      // pairs per block (M tile)
#define KC   32       // K per chunk (2 x k16 mma steps)
#define NCHK 20       // ceil(620/32)
#define NT   256      // 8 warps

#define MMAX 1024
#define PMAX 50176

#define XH   40       // Xs/Ws row stride in halfs (conflict-free for LDSM)
#define CST  168      // Ci row stride in floats

__device__ float  d_Apad[MMAX * HP];
__device__ float  d_Bpad[MMAX * HP];
__device__ float  d_distT[9 * HP];     // includes b1
__device__ float  d_genT[8 * HP];
__device__ float  d_spkT[3 * HP];
__device__ __half d_WtH[HP * 640];     // W1c^T fp16, [h][k] padded (zeros outside)
__device__ float  d_scores[PMAX];
__device__ int    d_starts[MMAX + 2];

// ---- f32x2 helpers for ab_k ----
union U2 { ull u; float f[2]; };
__device__ __forceinline__ ull pack2(float x, float y) { U2 v; v.f[0]=x; v.f[1]=y; return v.u; }
__device__ __forceinline__ void unpack2(ull v, float& x, float& y) { U2 t; t.u=v; x=t.f[0]; y=t.f[1]; }
__device__ __forceinline__ void fma2(ull& d, ull a, ull b) {
#if defined(__CUDA_ARCH__) && (__CUDA_ARCH__ >= 1000)
    asm("fma.rn.f32x2 %0, %1, %2, %3;" : "=l"(d) : "l"(a), "l"(b), "l"(d));
#else
    U2 dd,aa,bb; dd.u=d; aa.u=a; bb.u=b;
    dd.f[0]=fmaf(aa.f[0],bb.f[0],dd.f[0]); dd.f[1]=fmaf(aa.f[1],bb.f[1],dd.f[1]); d=dd.u;
#endif
}

__device__ __forceinline__ u32 s2u(const void* p) {
    u32 a;
    asm("{ .reg .u64 t; cvta.to.shared.u64 t, %1; cvt.u32.u64 %0, t; }" : "=r"(a) : "l"(p));
    return a;
}

#define MMA_F16(C, A, B0, B1)                                               \
    asm volatile("mma.sync.aligned.m16n8k16.row.col.f32.f16.f16.f32 "       \
        "{%0,%1,%2,%3}, {%4,%5,%6,%7}, {%8,%9}, {%0,%1,%2,%3};"             \
        : "+f"((C)[0]), "+f"((C)[1]), "+f"((C)[2]), "+f"((C)[3])            \
        : "r"((A)[0]), "r"((A)[1]), "r"((A)[2]), "r"((A)[3]),               \
          "r"(B0), "r"(B1))

#define LDSM4(R0, R1, R2, R3, ADDR)                                         \
    asm volatile("ldmatrix.sync.aligned.m8n8.x4.shared.b16 {%0,%1,%2,%3}, [%4];" \
        : "=r"(R0), "=r"(R1), "=r"(R2), "=r"(R3) : "r"(ADDR))

#define CP16(DST, SRC)                                                      \
    asm volatile("cp.async.ca.shared.global [%0], [%1], 16;" :: "r"(DST), "l"(SRC) : "memory")
#define CP_COMMIT() asm volatile("cp.async.commit_group;" ::: "memory")
#define CP_WAIT0()  asm volatile("cp.async.wait_group 0;"  ::: "memory")

// ---- shared layout (bytes). BIG region: Ci (init) aliases Xs/Ws (mainloop)
#define SM_SI   0
#define SM_SJ   512
#define SM_DB   1024
#define SM_GN   1536
#define SM_SP   2048
#define SM_W2   2560
#define SM_SRED 3200
#define SM_BIG  4224
#define CI_BYTES (TP * CST * 4)            // 86016
#define XSOFF(b) (SM_BIG + (b) * 23040)    // Xs: 128*40*2 = 10240
#define WSOFF(b) (XSOFF(b) + 10240)        // Ws: 160*40*2 = 12800
#define SM_TOT  (SM_BIG + CI_BYTES)        // 90240 -> 2 CTAs/SM

// ---------------------------------------------------------------------------
// prep_k: b0 phi tables (+b1 in distT), b1 starts, b in [2,402) W1c^T->fp16,
// rest output fill
// ---------------------------------------------------------------------------
__global__ void prep_k(float* __restrict__ out, int n,
                       const float* __restrict__ de, const float* __restrict__ ge,
                       const float* __restrict__ se, const float* __restrict__ W1,
                       const float* __restrict__ b1,
                       const int* __restrict__ mids, int P, int M) {
    int b = blockIdx.x;
    if (b == 0) {
        for (int e = threadIdx.x; e < 20 * HP; e += blockDim.x) {
            int row = e / HP, h = e % HP;
            const float* emb; int dbase; float* dst; float acc;
            if (row < 9)       { emb = de + row * 20;        dbase = 3 * GDIM;      dst = d_distT + row * HP + h;        acc = (h < HH) ? b1[h] : 0.0f; }
            else if (row < 17) { emb = ge + (row - 9) * 20;  dbase = 3 * GDIM + 20; dst = d_genT  + (row - 9) * HP + h;  acc = 0.0f; }
            else               { emb = se + (row - 17) * 20; dbase = 3 * GDIM + 40; dst = d_spkT  + (row - 17) * HP + h; acc = 0.0f; }
            if (h < HH) {
                #pragma unroll
                for (int k = 0; k < 20; k++) acc += emb[k] * W1[(dbase + k) * HH + h];
            }
            *dst = acc;
        }
    } else if (b == 1) {
        for (int m = threadIdx.x; m <= M; m += blockDim.x) {
            int lo = 0, hi = P;
            while (lo < hi) {
                int mid = (lo + hi) >> 1;
                if (mids[mid] < m) lo = mid + 1; else hi = mid;
            }
            d_starts[m] = lo;
        }
    } else if (b < 402) {
        int idx = (b - 2) * 256 + threadIdx.x;
        if (idx < HP * 640) {
            int h = idx / 640, k = idx % 640;
            const float* W1c = W1 + 2 * GDIM * HH;
            float v = (h < HH && k < GDIM) ? W1c[k * HH + h] : 0.0f;
            d_WtH[idx] = __float2half(v);
        }
    } else {
        int i = (b - 402) * blockDim.x + threadIdx.x;
        if (i < n) out[i] = (i == 0) ? 1.0f : 1000.0f;
    }
}

// ---------------------------------------------------------------------------
// ab_k: A = g@W1a (y=0), B = g@W1b (y=1). 8 mentions/block, f32x2 accs.
// ---------------------------------------------------------------------------
#define ABT 160
__global__ __launch_bounds__(ABT) void ab_k(const float* __restrict__ g,
                                            const float* __restrict__ W1, int M) {
    __shared__ float gs[GDIM][10];
    const int m0 = blockIdx.x * 8;
    const int which = blockIdx.y;
    const int tid = threadIdx.x;

    for (int e = tid; e < 8 * GDIM; e += ABT) {
        int mm = e / GDIM, d = e % GDIM;
        int m = m0 + mm;
        gs[d][mm] = (m < M) ? g[m * GDIM + d] : 0.0f;
    }
    __syncthreads();

    const int h = tid;
    ull acc[4] = {0ull, 0ull, 0ull, 0ull};
    if (h < HH) {
        const float* w = W1 + (which ? GDIM * HH : 0) + h;
        #pragma unroll 4
        for (int d = 0; d < GDIM; d++) {
            float wv = __ldg(&w[d * HH]);
            ull wp = pack2(wv, wv);
            const ull* grow = (const ull*)&gs[d][0];
            fma2(acc[0], grow[0], wp);
            fma2(acc[1], grow[1], wp);
            fma2(acc[2], grow[2], wp);
            fma2(acc[3], grow[3], wp);
        }
    }
    float* dst = which ? d_Bpad : d_Apad;
    #pragma unroll
    for (int r = 0; r < 4; r++) {
        float x, y; unpack2(acc[r], x, y);
        int m = m0 + 2 * r;
        if (m < M)     dst[m * HP + h] = x;
        if (m + 1 < M) dst[(m + 1) * HP + h] = y;
    }
}

// ---------------------------------------------------------------------------
// pair_k: 128 pairs x 160 h, 8 warps (4 m-blocks x 2 n-blocks). Exact fp32 C
// init; fp16 m16n8k16 Hadamard GEMM. Pipelined: 1 sync/chunk, ldmatrix frags,
// cp.async W fill, register-prefetched X fill. 2 CTAs/SM.
// ---------------------------------------------------------------------------
__global__ __launch_bounds__(NT, 2) void pair_k(
    const float* __restrict__ g,   const float* __restrict__ W2,
    const float* __restrict__ b2,  const float* __restrict__ ms,
    const int* __restrict__ mids,  const int* __restrict__ aids,
    const int* __restrict__ dists, const int* __restrict__ gens,
    const int* __restrict__ spks,  int P)
{
    extern __shared__ char smc[];
    int*   s_si = (int*)(smc + SM_SI);
    int*   s_sj = (int*)(smc + SM_SJ);
    int*   s_db = (int*)(smc + SM_DB);
    int*   s_gn = (int*)(smc + SM_GN);
    int*   s_sp = (int*)(smc + SM_SP);
    float* w2s  = (float*)(smc + SM_W2);
    float* sred = (float*)(smc + SM_SRED);
    float* Ci   = (float*)(smc + SM_BIG);

    const u32 smu = s2u(smc);
    const int tid = threadIdx.x;
    const int pb  = blockIdx.x * TP;

    if (tid < TP) {
        int p = pb + tid;
        bool ok = p < P;
        s_si[tid] = ok ? mids[p] : 0;
        s_sj[tid] = ok ? aids[p] : 0;
        int dd = ok ? dists[p] : 0;
        s_db[tid] = (dd >= 1) + (dd >= 2) + (dd >= 3) + (dd >= 4) +
                    (dd >= 8) + (dd >= 16) + (dd >= 32) + (dd >= 64);
        s_gn[tid] = ok ? gens[p] : 0;
        s_sp[tid] = ok ? spks[p] : 0;
    }
    if (tid < HP) w2s[tid] = (tid < HH) ? W2[tid] : 0.0f;
    __syncthreads();

    // ---- stage exact init tile Ci[128][160] (fp32)
    {
        const float4* A4 = (const float4*)d_Apad;
        const float4* B4 = (const float4*)d_Bpad;
        const float4* D4 = (const float4*)d_distT;
        const float4* G4 = (const float4*)d_genT;
        const float4* S4 = (const float4*)d_spkT;
        #pragma unroll
        for (int it = 0; it < (TP * 40) / NT; it++) {
            int e = tid + NT * it;
            int row = e / 40, c4 = e % 40;
            float4 a = __ldg(&A4[s_si[row] * 40 + c4]);
            float4 b = __ldg(&B4[s_sj[row] * 40 + c4]);
            float4 d = __ldg(&D4[s_db[row] * 40 + c4]);
            float4 gg = __ldg(&G4[s_gn[row] * 40 + c4]);
            float4 s = __ldg(&S4[s_sp[row] * 40 + c4]);
            float4 v = make_float4(a.x+b.x+d.x+gg.x+s.x, a.y+b.y+d.y+gg.y+s.y,
                                   a.z+b.z+d.z+gg.z+s.z, a.w+b.w+d.w+gg.w+s.w);
            *(float4*)(Ci + row * CST + c4 * 4) = v;
        }
    }
    __syncthreads();

    const int lid = tid & 31, wi = tid >> 5;
    const int mBlk = (wi & 3) * 32, nBlk = (wi >> 2) * 80;
    const int tig = lid & 3, grp = lid >> 2;

    // ---- load C fragments from Ci
    float c[2][10][4];
    #pragma unroll
    for (int ma = 0; ma < 2; ma++) {
        int r = mBlk + ma * 16 + grp;
        #pragma unroll
        for (int na = 0; na < 10; na++) {
            int col = nBlk + na * 8 + 2 * tig;
            float2 lo = *(const float2*)(Ci + r * CST + col);
            float2 hi = *(const float2*)(Ci + (r + 8) * CST + col);
            c[ma][na][0] = lo.x; c[ma][na][1] = lo.y;
            c[ma][na][2] = hi.x; c[ma][na][3] = hi.y;
        }
    }

    // ---- pipeline setup
    const int myrow = tid >> 1, par = tid & 1;
    const float4* gi4 = (const float4*)g + s_si[myrow] * 155;
    const float4* gj4 = (const float4*)g + s_sj[myrow] * 155;
    const char*   wsrc = (const char*)d_WtH + tid * 1280;   // row tid, bytes

    // ldmatrix lane address components
    const int aRow = ((lid >> 3) & 1) * 8 + (lid & 7);
    const int aK   = (lid >> 4) * 8;
    const int bRow = (lid >> 4) * 8 + (lid & 7);
    const int bK   = ((lid >> 3) & 1) * 8;

    uint4 st[2];
    // prefetch X chunk 0
    {
        __half2* h2 = (__half2*)st;
        #pragma unroll
        for (int q = 0; q < 4; q++) {
            int idx = par * 4 + q;
            float4 va = __ldg(gi4 + idx), vb = __ldg(gj4 + idx);
            h2[2*q]   = __floats2half2_rn(va.x * vb.x, va.y * vb.y);
            h2[2*q+1] = __floats2half2_rn(va.z * vb.z, va.w * vb.w);
        }
    }
    __syncthreads();   // Ci fragment reads complete; BIG region reusable

    // W chunk 0 via cp.async
    if (tid < HP) {
        u32 dst = smu + WSOFF(0) + tid * (XH * 2);
        const char* src = wsrc;
        CP16(dst, src); CP16(dst + 16, src + 16);
        CP16(dst + 32, src + 32); CP16(dst + 48, src + 48);
    }
    CP_COMMIT();

    for (int cch = 0; cch < NCHK; cch++) {
        const int buf = cch & 1;
        // store prefetched X chunk
        {
            uint4* dst = (uint4*)(smc + XSOFF(buf)) + myrow * 5 + par * 2;
            dst[0] = st[0]; dst[1] = st[1];
        }
        CP_WAIT0();          // W chunk cch arrived
        __syncthreads();     // publish buf; prior buf reads (cch-2) proven done

        if (cch + 1 < NCHK) {
            // W chunk cch+1
            if (tid < HP) {
                u32 dst = smu + WSOFF(buf ^ 1) + tid * (XH * 2);
                const char* src = wsrc + (cch + 1) * 64;
                CP16(dst, src); CP16(dst + 16, src + 16);
                CP16(dst + 32, src + 32); CP16(dst + 48, src + 48);
            }
            CP_COMMIT();
            // X chunk cch+1
            int k4 = (cch + 1) * 8 + par * 4;
            __half2* h2 = (__half2*)st;
            #pragma unroll
            for (int q = 0; q < 4; q++) {
                int idx = k4 + q;
                float4 va, vb;
                if (idx < 155) { va = __ldg(gi4 + idx); vb = __ldg(gj4 + idx); }
                else { va = make_float4(0.f,0.f,0.f,0.f); vb = va; }
                h2[2*q]   = __floats2half2_rn(va.x * vb.x, va.y * vb.y);
                h2[2*q+1] = __floats2half2_rn(va.z * vb.z, va.w * vb.w);
            }
        }

        // ---- mma on buf: 2 x k16 steps, ldmatrix fragments
        const u32 xb = smu + XSOFF(buf);
        const u32 wb = smu + WSOFF(buf);
        #pragma unroll
        for (int s = 0; s < 2; s++) {
            u32 a[2][4];
            #pragma unroll
            for (int ma = 0; ma < 2; ma++) {
                u32 ad = xb + ((mBlk + ma * 16 + aRow) * XH + s * 16 + aK) * 2;
                LDSM4(a[ma][0], a[ma][1], a[ma][2], a[ma][3], ad);
            }
            #pragma unroll
            for (int np = 0; np < 5; np++) {
                u32 ad = wb + ((nBlk + np * 16 + bRow) * XH + s * 16 + bK) * 2;
                u32 b0, b1, b2, b3;
                LDSM4(b0, b1, b2, b3, ad);
                MMA_F16(c[0][2*np],     a[0], b0, b1);
                MMA_F16(c[1][2*np],     a[1], b0, b1);
                MMA_F16(c[0][2*np + 1], a[0], b2, b3);
                MMA_F16(c[1][2*np + 1], a[1], b2, b3);
            }
        }
    }

    // ---- epilogue: relu + dot W2, reduce over tig, combine n-blocks
    float part[2][2] = {{0.f, 0.f}, {0.f, 0.f}};
    #pragma unroll
    for (int ma = 0; ma < 2; ma++)
        #pragma unroll
        for (int na = 0; na < 10; na++) {
            int col = nBlk + na * 8 + 2 * tig;
            float w0 = w2s[col], w1 = w2s[col + 1];
            float v0 = fmaxf(c[ma][na][0], 0.f), v1 = fmaxf(c[ma][na][1], 0.f);
            float v2 = fmaxf(c[ma][na][2], 0.f), v3 = fmaxf(c[ma][na][3], 0.f);
            part[ma][0] += v0 * w0 + v1 * w1;
            part[ma][1] += v2 * w0 + v3 * w1;
        }
    #pragma unroll
    for (int ma = 0; ma < 2; ma++)
        #pragma unroll
        for (int rr = 0; rr < 2; rr++) {
            float v = part[ma][rr];
            v += __shfl_xor_sync(0xffffffffu, v, 1);
            v += __shfl_xor_sync(0xffffffffu, v, 2);
            part[ma][rr] = v;
        }
    if (tig == 0) {
        int nb = wi >> 2;
        #pragma unroll
        for (int ma = 0; ma < 2; ma++)
            #pragma unroll
            for (int rr = 0; rr < 2; rr++) {
                int row = mBlk + ma * 16 + grp + 8 * rr;
                sred[row * 2 + nb] = part[ma][rr];
            }
    }
    __syncthreads();
    if (tid < TP) {
        int p = pb + tid;
        if (p < P) {
            float s = sred[tid * 2] + sred[tid * 2 + 1];
            d_scores[p] = s + __ldg(b2) + ms[s_si[tid]] + ms[s_sj[tid]];
        }
    }
}

// ---------------------------------------------------------------------------
// Ragged softmax (+epsilon logit 0), one warp per mention
// ---------------------------------------------------------------------------
__global__ void softmax_k(float* __restrict__ out, int M) {
    int warp = (blockIdx.x * blockDim.x + threadIdx.x) >> 5;
    int lane = threadIdx.x & 31;
    if (warp >= M) return;
    int s0 = d_starts[warp], s1 = d_starts[warp + 1];
    int n = s1 - s0;

    float mx = 0.0f;
    for (int i = lane; i < n; i += 32) mx = fmaxf(mx, d_scores[s0 + i]);
    #pragma unroll
    for (int off = 16; off; off >>= 1) mx = fmaxf(mx, __shfl_xor_sync(0xffffffffu, mx, off));

    float sum = 0.0f;
    for (int i = lane; i < n; i += 32) sum += expf(d_scores[s0 + i] - mx);
    #pragma unroll
    for (int off = 16; off; off >>= 1) sum += __shfl_xor_sync(0xffffffffu, sum, off);

    float eps = expf(-mx);
    float inv = 1.0f / (sum + eps);
    float* row = out + (warp + 1) * 161;
    for (int i = lane; i < n; i += 32) row[i] = expf(d_scores[s0 + i] - mx) * inv;
    if (lane == 0) row[n] = eps * inv;
}

// ---------------------------------------------------------------------------
extern "C" void kernel_launch(void* const* d_in, const int* in_sizes, int n_in,
                              void* d_out, int out_size) {
    const float* g_i   = (const float*)d_in[0];
    const float* msc   = (const float*)d_in[1];
    const float* de    = (const float*)d_in[2];
    const float* ge    = (const float*)d_in[3];
    const float* se    = (const float*)d_in[4];
    const float* W1    = (const float*)d_in[5];
    const float* b1    = (const float*)d_in[6];
    const float* W2    = (const float*)d_in[7];
    const float* b2    = (const float*)d_in[8];
    const int*   mids  = (const int*)d_in[9];
    const int*   aids  = (const int*)d_in[10];
    const int*   dists = (const int*)d_in[11];
    const int*   gens  = (const int*)d_in[12];
    const int*   spks  = (const int*)d_in[13];

    int M = in_sizes[1];
    int P = in_sizes[9];
    float* out = (float*)d_out;

    cudaFuncSetAttribute(pair_k, cudaFuncAttributeMaxDynamicSharedMemorySize, SM_TOT);

    prep_k<<<402 + (out_size + 255) / 256, 256>>>(out, out_size, de, ge, se, W1, b1, mids, P, M);
    ab_k<<<dim3((M + 7) / 8, 2), ABT>>>(g_i, W1, M);
    pair_k<<<(P + TP - 1) / TP, NT, SM_TOT>>>(g_i, W2, b2, msc,
                                              mids, aids, dists, gens, spks, P);
    softmax_k<<<(M + 7) / 8, 256>>>(out, M);
}

// round 9
// speedup vs baseline: 3.6685x; 1.1101x over previous
#include <cuda_runtime.h>
#include <cuda_fp16.h>

typedef unsigned int u32;
typedef unsigned long long ull;

#define GDIM 620
#define HH   150
#define HP   160
#define TP   64       // pairs per block (M tile)
#define NCHK 20       // 640/32
#define NT   256      // 8 warps: 2 m-blocks x 4 n-blocks

#define MMAX 1024
#define PMAX 50176

#define XH   40       // Xs/Ws row stride in halfs (LDSM conflict-free)
#define CST  168      // Ci row stride in floats

__device__ float  d_Apad[MMAX * HP];
__device__ float  d_Bpad[MMAX * HP];
__device__ float  d_distT[9 * HP];     // includes b1
__device__ float  d_genT[8 * HP];
__device__ float  d_spkT[3 * HP];
__device__ __half d_WtH[HP * 640];     // W1c^T fp16, [h][k], zero padded
__device__ __half d_g16[MMAX * 640];   // g fp16, row stride 640, zero padded
__device__ float  d_scores[PMAX];
__device__ int    d_starts[MMAX + 2];

// ---- f32x2 helpers for ab_k ----
union U2 { ull u; float f[2]; };
__device__ __forceinline__ ull pack2(float x, float y) { U2 v; v.f[0]=x; v.f[1]=y; return v.u; }
__device__ __forceinline__ void unpack2(ull v, float& x, float& y) { U2 t; t.u=v; x=t.f[0]; y=t.f[1]; }
__device__ __forceinline__ void fma2(ull& d, ull a, ull b) {
#if defined(__CUDA_ARCH__) && (__CUDA_ARCH__ >= 1000)
    asm("fma.rn.f32x2 %0, %1, %2, %3;" : "=l"(d) : "l"(a), "l"(b), "l"(d));
#else
    U2 dd,aa,bb; dd.u=d; aa.u=a; bb.u=b;
    dd.f[0]=fmaf(aa.f[0],bb.f[0],dd.f[0]); dd.f[1]=fmaf(aa.f[1],bb.f[1],dd.f[1]); d=dd.u;
#endif
}

__device__ __forceinline__ u32 s2u(const void* p) {
    u32 a;
    asm("{ .reg .u64 t; cvta.to.shared.u64 t, %1; cvt.u32.u64 %0, t; }" : "=r"(a) : "l"(p));
    return a;
}

#define MMA_F16(C, A, B0, B1)                                               \
    asm volatile("mma.sync.aligned.m16n8k16.row.col.f32.f16.f16.f32 "       \
        "{%0,%1,%2,%3}, {%4,%5,%6,%7}, {%8,%9}, {%0,%1,%2,%3};"             \
        : "+f"((C)[0]), "+f"((C)[1]), "+f"((C)[2]), "+f"((C)[3])            \
        : "r"((A)[0]), "r"((A)[1]), "r"((A)[2]), "r"((A)[3]),               \
          "r"(B0), "r"(B1))

#define LDSM4(R0, R1, R2, R3, ADDR)                                         \
    asm volatile("ldmatrix.sync.aligned.m8n8.x4.shared.b16 {%0,%1,%2,%3}, [%4];" \
        : "=r"(R0), "=r"(R1), "=r"(R2), "=r"(R3) : "r"(ADDR))
#define LDSM2(R0, R1, ADDR)                                                 \
    asm volatile("ldmatrix.sync.aligned.m8n8.x2.shared.b16 {%0,%1}, [%2];"  \
        : "=r"(R0), "=r"(R1) : "r"(ADDR))

#define CP16(DST, SRC)                                                      \
    asm volatile("cp.async.ca.shared.global [%0], [%1], 16;" :: "r"(DST), "l"(SRC) : "memory")
#define CP_COMMIT() asm volatile("cp.async.commit_group;" ::: "memory")
#define CP_WAIT0()  asm volatile("cp.async.wait_group 0;"  ::: "memory")

// ---- shared layout (bytes). BIG: Ci (init) aliases Xs/Ws (mainloop)
#define SM_SI   0
#define SM_SJ   256
#define SM_DB   512
#define SM_GN   768
#define SM_SP   1024
#define SM_W2   1280
#define SM_SRED 1920                   // 64*4 floats = 1024B
#define SM_BIG  2944
#define CI_BYTES (TP * CST * 4)        // 43008
#define XSOFF(b) (SM_BIG + (b) * 17920)   // Xs: 64*40*2 = 5120
#define WSOFF(b) (XSOFF(b) + 5120)        // Ws: 160*40*2 = 12800
#define SM_TOT  (SM_BIG + CI_BYTES)    // 45952 -> 3 CTAs/SM (regs permitting)

// ---------------------------------------------------------------------------
// prep_k: b0 tables, b1 starts, [2,402) WtH fp16, [402,402+nG16) g fp16,
// rest output fill
// ---------------------------------------------------------------------------
__global__ void prep_k(float* __restrict__ out, int n,
                       const float* __restrict__ de, const float* __restrict__ ge,
                       const float* __restrict__ se, const float* __restrict__ W1,
                       const float* __restrict__ b1, const float* __restrict__ g,
                       const int* __restrict__ mids, int P, int M, int nG16) {
    int b = blockIdx.x;
    if (b == 0) {
        for (int e = threadIdx.x; e < 20 * HP; e += blockDim.x) {
            int row = e / HP, h = e % HP;
            const float* emb; int dbase; float* dst; float acc;
            if (row < 9)       { emb = de + row * 20;        dbase = 3 * GDIM;      dst = d_distT + row * HP + h;        acc = (h < HH) ? b1[h] : 0.0f; }
            else if (row < 17) { emb = ge + (row - 9) * 20;  dbase = 3 * GDIM + 20; dst = d_genT  + (row - 9) * HP + h;  acc = 0.0f; }
            else               { emb = se + (row - 17) * 20; dbase = 3 * GDIM + 40; dst = d_spkT  + (row - 17) * HP + h; acc = 0.0f; }
            if (h < HH) {
                #pragma unroll
                for (int k = 0; k < 20; k++) acc += emb[k] * W1[(dbase + k) * HH + h];
            }
            *dst = acc;
        }
    } else if (b == 1) {
        for (int m = threadIdx.x; m <= M; m += blockDim.x) {
            int lo = 0, hi = P;
            while (lo < hi) {
                int mid = (lo + hi) >> 1;
                if (mids[mid] < m) lo = mid + 1; else hi = mid;
            }
            d_starts[m] = lo;
        }
    } else if (b < 402) {
        int idx = (b - 2) * 256 + threadIdx.x;
        if (idx < HP * 640) {
            int h = idx / 640, k = idx % 640;
            const float* W1c = W1 + 2 * GDIM * HH;
            float v = (h < HH && k < GDIM) ? W1c[k * HH + h] : 0.0f;
            d_WtH[idx] = __float2half(v);
        }
    } else if (b < 402 + nG16) {
        int idx = (b - 402) * 256 + threadIdx.x;
        if (idx < M * 640) {
            int m = idx / 640, k = idx % 640;
            float v = (k < GDIM) ? g[m * GDIM + k] : 0.0f;
            d_g16[idx] = __float2half(v);
        }
    } else {
        int i = (b - 402 - nG16) * blockDim.x + threadIdx.x;
        if (i < n) out[i] = (i == 0) ? 1.0f : 1000.0f;
    }
}

// ---------------------------------------------------------------------------
// ab_k: A = g@W1a (y=0), B = g@W1b (y=1). 8 mentions/block, f32x2 accs.
// ---------------------------------------------------------------------------
#define ABT 160
__global__ __launch_bounds__(ABT) void ab_k(const float* __restrict__ g,
                                            const float* __restrict__ W1, int M) {
    __shared__ float gs[GDIM][10];
    const int m0 = blockIdx.x * 8;
    const int which = blockIdx.y;
    const int tid = threadIdx.x;

    for (int e = tid; e < 8 * GDIM; e += ABT) {
        int mm = e / GDIM, d = e % GDIM;
        int m = m0 + mm;
        gs[d][mm] = (m < M) ? g[m * GDIM + d] : 0.0f;
    }
    __syncthreads();

    const int h = tid;
    ull acc[4] = {0ull, 0ull, 0ull, 0ull};
    if (h < HH) {
        const float* w = W1 + (which ? GDIM * HH : 0) + h;
        #pragma unroll 4
        for (int d = 0; d < GDIM; d++) {
            float wv = __ldg(&w[d * HH]);
            ull wp = pack2(wv, wv);
            const ull* grow = (const ull*)&gs[d][0];
            fma2(acc[0], grow[0], wp);
            fma2(acc[1], grow[1], wp);
            fma2(acc[2], grow[2], wp);
            fma2(acc[3], grow[3], wp);
        }
    }
    float* dst = which ? d_Bpad : d_Apad;
    #pragma unroll
    for (int r = 0; r < 4; r++) {
        float x, y; unpack2(acc[r], x, y);
        int m = m0 + 2 * r;
        if (m < M)     dst[m * HP + h] = x;
        if (m + 1 < M) dst[(m + 1) * HP + h] = y;
    }
}

// ---------------------------------------------------------------------------
// pair_k: 64 pairs x 160 h per CTA, 8 warps = 2 m-blocks(32) x 4 n-blocks(40).
// Exact fp32 C init; fp16 m16n8k16 Hadamard GEMM; fp16 g source. 3 CTAs/SM.
// ---------------------------------------------------------------------------
__global__ __launch_bounds__(NT, 3) void pair_k(
    const float* __restrict__ W2,  const float* __restrict__ b2,
    const float* __restrict__ ms,
    const int* __restrict__ mids,  const int* __restrict__ aids,
    const int* __restrict__ dists, const int* __restrict__ gens,
    const int* __restrict__ spks,  int P)
{
    extern __shared__ char smc[];
    int*   s_si = (int*)(smc + SM_SI);
    int*   s_sj = (int*)(smc + SM_SJ);
    int*   s_db = (int*)(smc + SM_DB);
    int*   s_gn = (int*)(smc + SM_GN);
    int*   s_sp = (int*)(smc + SM_SP);
    float* w2s  = (float*)(smc + SM_W2);
    float* sred = (float*)(smc + SM_SRED);
    float* Ci   = (float*)(smc + SM_BIG);

    const u32 smu = s2u(smc);
    const int tid = threadIdx.x;
    const int pb  = blockIdx.x * TP;

    if (tid < TP) {
        int p = pb + tid;
        bool ok = p < P;
        s_si[tid] = ok ? mids[p] : 0;
        s_sj[tid] = ok ? aids[p] : 0;
        int dd = ok ? dists[p] : 0;
        s_db[tid] = (dd >= 1) + (dd >= 2) + (dd >= 3) + (dd >= 4) +
                    (dd >= 8) + (dd >= 16) + (dd >= 32) + (dd >= 64);
        s_gn[tid] = ok ? gens[p] : 0;
        s_sp[tid] = ok ? spks[p] : 0;
    }
    if (tid < HP) w2s[tid] = (tid < HH) ? W2[tid] : 0.0f;
    __syncthreads();

    // ---- stage exact init tile Ci[64][160] (fp32)
    {
        const float4* A4 = (const float4*)d_Apad;
        const float4* B4 = (const float4*)d_Bpad;
        const float4* D4 = (const float4*)d_distT;
        const float4* G4 = (const float4*)d_genT;
        const float4* S4 = (const float4*)d_spkT;
        #pragma unroll
        for (int it = 0; it < (TP * 40) / NT; it++) {
            int e = tid + NT * it;
            int row = e / 40, c4 = e % 40;
            float4 a = __ldg(&A4[s_si[row] * 40 + c4]);
            float4 b = __ldg(&B4[s_sj[row] * 40 + c4]);
            float4 d = __ldg(&D4[s_db[row] * 40 + c4]);
            float4 gg = __ldg(&G4[s_gn[row] * 40 + c4]);
            float4 s = __ldg(&S4[s_sp[row] * 40 + c4]);
            float4 v = make_float4(a.x+b.x+d.x+gg.x+s.x, a.y+b.y+d.y+gg.y+s.y,
                                   a.z+b.z+d.z+gg.z+s.z, a.w+b.w+d.w+gg.w+s.w);
            *(float4*)(Ci + row * CST + c4 * 4) = v;
        }
    }
    __syncthreads();

    const int lid = tid & 31, wi = tid >> 5;
    const int mBlk = (wi & 1) * 32, nBlk = (wi >> 1) * 40;
    const int tig = lid & 3, grp = lid >> 2;

    // ---- load C fragments from Ci (2 m-atoms x 5 n-atoms)
    float c[2][5][4];
    #pragma unroll
    for (int ma = 0; ma < 2; ma++) {
        int r = mBlk + ma * 16 + grp;
        #pragma unroll
        for (int na = 0; na < 5; na++) {
            int col = nBlk + na * 8 + 2 * tig;
            float2 lo = *(const float2*)(Ci + r * CST + col);
            float2 hi = *(const float2*)(Ci + (r + 8) * CST + col);
            c[ma][na][0] = lo.x; c[ma][na][1] = lo.y;
            c[ma][na][2] = hi.x; c[ma][na][3] = hi.y;
        }
    }

    // ---- pipeline setup
    const int myrow = tid >> 2, q = tid & 3;          // row 0..63, quarter 0..3
    const uint4* gi16 = (const uint4*)(d_g16 + s_si[myrow] * 640) + q;  // +q*8 halfs
    const uint4* gj16 = (const uint4*)(d_g16 + s_sj[myrow] * 640) + q;
    const char*  wsrc = (const char*)d_WtH + tid * 1280;   // row tid (if <160)

    // ldmatrix lane address components
    const int aRow = ((lid >> 3) & 1) * 8 + (lid & 7);
    const int aK   = (lid >> 4) * 8;
    const int bRow = (lid >> 4) * 8 + (lid & 7);
    const int bK   = ((lid >> 3) & 1) * 8;
    const int b2r  = nBlk + 32 + (lid & 7);           // LDSM2: last 8 cols
    const int b2k  = ((lid >> 3) & 1) * 8;

    uint4 xi, xj;
    xi = __ldg(gi16);   // chunk 0 (uint4 index stride 4 per chunk: 32 halfs)
    xj = __ldg(gj16);
    __syncthreads();   // Ci fragment reads done; BIG region reusable

    if (tid < HP) {    // W chunk 0
        u32 dst = smu + WSOFF(0) + tid * (XH * 2);
        CP16(dst, wsrc); CP16(dst + 16, wsrc + 16);
        CP16(dst + 32, wsrc + 32); CP16(dst + 48, wsrc + 48);
    }
    CP_COMMIT();

    for (int cch = 0; cch < NCHK; cch++) {
        const int buf = cch & 1;
        // store prefetched X chunk: 4 x hmul2 -> 16B
        {
            const __half2* a2 = (const __half2*)&xi;
            const __half2* b2h = (const __half2*)&xj;
            uint4 st;
            __half2* o2 = (__half2*)&st;
            #pragma unroll
            for (int k = 0; k < 4; k++) o2[k] = __hmul2(a2[k], b2h[k]);
            *((uint4*)(smc + XSOFF(buf)) + myrow * 5 + q) = st;
        }
        CP_WAIT0();
        __syncthreads();

        if (cch + 1 < NCHK) {
            if (tid < HP) {
                u32 dst = smu + WSOFF(buf ^ 1) + tid * (XH * 2);
                const char* src = wsrc + (cch + 1) * 64;
                CP16(dst, src); CP16(dst + 16, src + 16);
                CP16(dst + 32, src + 32); CP16(dst + 48, src + 48);
            }
            CP_COMMIT();
            xi = __ldg(gi16 + (cch + 1) * 4);
            xj = __ldg(gj16 + (cch + 1) * 4);
        }

        // ---- mma on buf: 2 x k16 steps
        const u32 xb = smu + XSOFF(buf);
        const u32 wb = smu + WSOFF(buf);
        #pragma unroll
        for (int s = 0; s < 2; s++) {
            u32 a[2][4];
            #pragma unroll
            for (int ma = 0; ma < 2; ma++) {
                u32 ad = xb + ((mBlk + ma * 16 + aRow) * XH + s * 16 + aK) * 2;
                LDSM4(a[ma][0], a[ma][1], a[ma][2], a[ma][3], ad);
            }
            #pragma unroll
            for (int ng = 0; ng < 2; ng++) {
                u32 ad = wb + ((nBlk + ng * 16 + bRow) * XH + s * 16 + bK) * 2;
                u32 b0, b1, b2v, b3;
                LDSM4(b0, b1, b2v, b3, ad);
                MMA_F16(c[0][2*ng],     a[0], b0, b1);
                MMA_F16(c[1][2*ng],     a[1], b0, b1);
                MMA_F16(c[0][2*ng + 1], a[0], b2v, b3);
                MMA_F16(c[1][2*ng + 1], a[1], b2v, b3);
            }
            {   // last 8 cols
                u32 ad = wb + (b2r * XH + s * 16 + b2k) * 2;
                u32 b0, b1;
                LDSM2(b0, b1, ad);
                MMA_F16(c[0][4], a[0], b0, b1);
                MMA_F16(c[1][4], a[1], b0, b1);
            }
        }
    }

    // ---- epilogue: relu + dot W2, reduce over tig, combine 4 n-blocks
    float part[2][2] = {{0.f, 0.f}, {0.f, 0.f}};
    #pragma unroll
    for (int ma = 0; ma < 2; ma++)
        #pragma unroll
        for (int na = 0; na < 5; na++) {
            int col = nBlk + na * 8 + 2 * tig;
            float w0 = w2s[col], w1 = w2s[col + 1];
            float v0 = fmaxf(c[ma][na][0], 0.f), v1 = fmaxf(c[ma][na][1], 0.f);
            float v2 = fmaxf(c[ma][na][2], 0.f), v3 = fmaxf(c[ma][na][3], 0.f);
            part[ma][0] += v0 * w0 + v1 * w1;
            part[ma][1] += v2 * w0 + v3 * w1;
        }
    #pragma unroll
    for (int ma = 0; ma < 2; ma++)
        #pragma unroll
        for (int rr = 0; rr < 2; rr++) {
            float v = part[ma][rr];
            v += __shfl_xor_sync(0xffffffffu, v, 1);
            v += __shfl_xor_sync(0xffffffffu, v, 2);
            part[ma][rr] = v;
        }
    if (tig == 0) {
        int nb = wi >> 1;
        #pragma unroll
        for (int ma = 0; ma < 2; ma++)
            #pragma unroll
            for (int rr = 0; rr < 2; rr++) {
                int row = mBlk + ma * 16 + grp + 8 * rr;
                sred[row * 4 + nb] = part[ma][rr];
            }
    }
    __syncthreads();
    if (tid < TP) {
        int p = pb + tid;
        if (p < P) {
            float s = sred[tid * 4] + sred[tid * 4 + 1] +
                      sred[tid * 4 + 2] + sred[tid * 4 + 3];
            d_scores[p] = s + __ldg(b2) + ms[s_si[tid]] + ms[s_sj[tid]];
        }
    }
}

// ---------------------------------------------------------------------------
// Ragged softmax (+epsilon logit 0), one warp per mention
// ---------------------------------------------------------------------------
__global__ void softmax_k(float* __restrict__ out, int M) {
    int warp = (blockIdx.x * blockDim.x + threadIdx.x) >> 5;
    int lane = threadIdx.x & 31;
    if (warp >= M) return;
    int s0 = d_starts[warp], s1 = d_starts[warp + 1];
    int n = s1 - s0;

    float mx = 0.0f;
    for (int i = lane; i < n; i += 32) mx = fmaxf(mx, d_scores[s0 + i]);
    #pragma unroll
    for (int off = 16; off; off >>= 1) mx = fmaxf(mx, __shfl_xor_sync(0xffffffffu, mx, off));

    float sum = 0.0f;
    for (int i = lane; i < n; i += 32) sum += expf(d_scores[s0 + i] - mx);
    #pragma unroll
    for (int off = 16; off; off >>= 1) sum += __shfl_xor_sync(0xffffffffu, sum, off);

    float eps = expf(-mx);
    float inv = 1.0f / (sum + eps);
    float* row = out + (warp + 1) * 161;
    for (int i = lane; i < n; i += 32) row[i] = expf(d_scores[s0 + i] - mx) * inv;
    if (lane == 0) row[n] = eps * inv;
}

// ---------------------------------------------------------------------------
extern "C" void kernel_launch(void* const* d_in, const int* in_sizes, int n_in,
                              void* d_out, int out_size) {
    const float* g_i   = (const float*)d_in[0];
    const float* msc   = (const float*)d_in[1];
    const float* de    = (const float*)d_in[2];
    const float* ge    = (const float*)d_in[3];
    const float* se    = (const float*)d_in[4];
    const float* W1    = (const float*)d_in[5];
    const float* b1    = (const float*)d_in[6];
    const float* W2    = (const float*)d_in[7];
    const float* b2    = (const float*)d_in[8];
    const int*   mids  = (const int*)d_in[9];
    const int*   aids  = (const int*)d_in[10];
    const int*   dists = (const int*)d_in[11];
    const int*   gens  = (const int*)d_in[12];
    const int*   spks  = (const int*)d_in[13];

    int M = in_sizes[1];
    int P = in_sizes[9];
    float* out = (float*)d_out;

    int nG16  = (M * 640 + 255) / 256;
    int fillB = (out_size + 255) / 256;

    cudaFuncSetAttribute(pair_k, cudaFuncAttributeMaxDynamicSharedMemorySize, SM_TOT);

    prep_k<<<402 + nG16 + fillB, 256>>>(out, out_size, de, ge, se, W1, b1, g_i,
                                        mids, P, M, nG16);
    ab_k<<<dim3((M + 7) / 8, 2), ABT>>>(g_i, W1, M);
    pair_k<<<(P + TP - 1) / TP, NT, SM_TOT>>>(W2, b2, msc,
                                              mids, aids, dists, gens, spks, P);
    softmax_k<<<(M + 7) / 8, 256>>>(out, M);
}